// round 2
// baseline (speedup 1.0000x reference)
#include <cuda_runtime.h>
#include <math.h>

#define B_SZ 32
#define L_SZ 32768
#define PS_SZ 32
#define T_SZ 1024
#define D_SZ 256
#define NTOK (B_SZ * T_SZ)   // 32768

// ---------------- scratch (no allocs allowed; BSS device globals) ----------------
__device__ float g_xn[B_SZ * L_SZ];          // normalized series / patches (4 MB)
__device__ float g_h[NTOK * D_SZ];           // patch embedding (32 MB)
__device__ float g_qkv[NTOK * 3 * D_SZ];     // qkv (96 MB)
__device__ float g_attn[NTOK * D_SZ];        // attention out (32 MB)
__device__ float g_out2[NTOK * D_SZ];        // after W_out (32 MB)
__device__ float g_partial[4096];            // per-block loss partials

// ---------------- 1) instance norm over full series (ddof=1) ----------------
__global__ __launch_bounds__(1024) void norm_kernel(const float* __restrict__ x) {
    int b = blockIdx.x;
    const float* xr = x + (size_t)b * L_SZ;
    float s = 0.f, sq = 0.f;
    for (int i = threadIdx.x; i < L_SZ; i += 1024) {
        float v = xr[i];
        s += v; sq += v * v;
    }
    for (int o = 16; o > 0; o >>= 1) {
        s  += __shfl_xor_sync(0xffffffffu, s,  o);
        sq += __shfl_xor_sync(0xffffffffu, sq, o);
    }
    __shared__ float ss[32], ssq[32];
    __shared__ float sm_mean, sm_inv;
    int w = threadIdx.x >> 5;
    if ((threadIdx.x & 31) == 0) { ss[w] = s; ssq[w] = sq; }
    __syncthreads();
    if (threadIdx.x == 0) {
        float S = 0.f, SQ = 0.f;
        #pragma unroll
        for (int i = 0; i < 32; i++) { S += ss[i]; SQ += ssq[i]; }
        float mean = S / (float)L_SZ;
        float var = (SQ - (float)L_SZ * mean * mean) / (float)(L_SZ - 1);
        sm_mean = mean;
        sm_inv = 1.0f / (sqrtf(var) + 1e-5f);
    }
    __syncthreads();
    float mean = sm_mean, inv = sm_inv;
    float* op = g_xn + (size_t)b * L_SZ;
    for (int i = threadIdx.x; i < L_SZ; i += 1024)
        op[i] = (xr[i] - mean) * inv;
}

// ---------------- 2) generic SGEMM: C[M,N] = A[M,K] @ B[K,N] + bias ----------------
// BM=BN=128, BK=8, 256 threads, 8x8 register tiles. Requires M%128==0, N%128==0, K%8==0.
__global__ __launch_bounds__(256) void sgemm_bias(const float* __restrict__ A,
                                                  const float* __restrict__ Bm,
                                                  const float* __restrict__ bias,
                                                  float* __restrict__ C,
                                                  int M, int N, int K) {
    __shared__ float As[8][128];
    __shared__ float Bs[8][128];
    int tid = threadIdx.x;
    int bm = blockIdx.y * 128, bn = blockIdx.x * 128;
    int arow = tid >> 1, acol = (tid & 1) << 2;
    int brow = tid >> 5, bcol = (tid & 31) << 2;
    int tr = (tid >> 4) << 3, tc = (tid & 15) << 3;

    float acc[8][8];
    #pragma unroll
    for (int i = 0; i < 8; i++)
        #pragma unroll
        for (int j = 0; j < 8; j++) acc[i][j] = 0.f;

    for (int k0 = 0; k0 < K; k0 += 8) {
        float4 a4 = *(const float4*)(A + (size_t)(bm + arow) * K + k0 + acol);
        As[acol + 0][arow] = a4.x;
        As[acol + 1][arow] = a4.y;
        As[acol + 2][arow] = a4.z;
        As[acol + 3][arow] = a4.w;
        *(float4*)&Bs[brow][bcol] =
            *(const float4*)(Bm + (size_t)(k0 + brow) * N + bn + bcol);
        __syncthreads();
        #pragma unroll
        for (int k = 0; k < 8; k++) {
            float ar[8], br[8];
            *(float4*)&ar[0] = *(float4*)&As[k][tr];
            *(float4*)&ar[4] = *(float4*)&As[k][tr + 4];
            *(float4*)&br[0] = *(float4*)&Bs[k][tc];
            *(float4*)&br[4] = *(float4*)&Bs[k][tc + 4];
            #pragma unroll
            for (int i = 0; i < 8; i++)
                #pragma unroll
                for (int j = 0; j < 8; j++)
                    acc[i][j] += ar[i] * br[j];
        }
        __syncthreads();
    }
    float bz[8];
    #pragma unroll
    for (int j = 0; j < 8; j++) bz[j] = bias[bn + tc + j];
    #pragma unroll
    for (int i = 0; i < 8; i++) {
        int row = bm + tr + i;
        float4 o0, o1;
        o0.x = acc[i][0] + bz[0];
        o0.y = acc[i][1] + bz[1];
        o0.z = acc[i][2] + bz[2];
        o0.w = acc[i][3] + bz[3];
        o1.x = acc[i][4] + bz[4];
        o1.y = acc[i][5] + bz[5];
        o1.z = acc[i][6] + bz[6];
        o1.w = acc[i][7] + bz[7];
        *(float4*)(C + (size_t)row * N + bn + tc)     = o0;
        *(float4*)(C + (size_t)row * N + bn + tc + 4) = o1;
    }
}

// ---------------- 3) causal flash attention, fp32 ----------------
// Per CTA: one batch b, one 64-row Q block. K/V streamed in 64-row tiles.
// smem: Qt[256][68] + Kt[256][68] + Vs[64][256] + Ps[64][68] = 222208 B (dynamic).
#define QKT_STRIDE 68
#define FA_SMEM ((256 * QKT_STRIDE * 2 + 64 * 256 + 64 * QKT_STRIDE) * 4)

__global__ __launch_bounds__(256) void flash_kernel(const float* __restrict__ qkv,
                                                    float* __restrict__ outp) {
    extern __shared__ float smem[];
    float* Qt = smem;                        // [256][68] k-major
    float* Kt = Qt + 256 * QKT_STRIDE;       // [256][68] k-major
    float* Vs = Kt + 256 * QKT_STRIDE;       // [64][256] row-major
    float* Ps = Vs + 64 * 256;               // [64][68]

    int b = blockIdx.y;
    int qb = (int)gridDim.x - 1 - (int)blockIdx.x;   // heavy q-blocks scheduled first
    int tid = threadIdx.x;
    int tx = tid & 15, ty = tid >> 4;
    const float* base = qkv + (size_t)b * T_SZ * (3 * D_SZ);

    // Load Q tile transposed (k-major) into smem
    for (int i = tid; i < 64 * 64; i += 256) {
        int row = i >> 6;
        int c4 = (i & 63) << 2;
        float4 v = *(const float4*)(base + (size_t)(qb * 64 + row) * 768 + c4);
        Qt[(c4 + 0) * QKT_STRIDE + row] = v.x;
        Qt[(c4 + 1) * QKT_STRIDE + row] = v.y;
        Qt[(c4 + 2) * QKT_STRIDE + row] = v.z;
        Qt[(c4 + 3) * QKT_STRIDE + row] = v.w;
    }

    float m_i[4], l_i[4], o[4][16];
    #pragma unroll
    for (int i = 0; i < 4; i++) {
        m_i[i] = -3.0e38f;
        l_i[i] = 0.f;
        #pragma unroll
        for (int j = 0; j < 16; j++) o[i][j] = 0.f;
    }

    for (int kb = 0; kb <= qb; kb++) {
        __syncthreads();  // previous iteration's PV reads of Vs done
        for (int i = tid; i < 64 * 64; i += 256) {
            int row = i >> 6;
            int c4 = (i & 63) << 2;
            const float* kbase = base + (size_t)(kb * 64 + row) * 768;
            float4 kv = *(const float4*)(kbase + 256 + c4);
            Kt[(c4 + 0) * QKT_STRIDE + row] = kv.x;
            Kt[(c4 + 1) * QKT_STRIDE + row] = kv.y;
            Kt[(c4 + 2) * QKT_STRIDE + row] = kv.z;
            Kt[(c4 + 3) * QKT_STRIDE + row] = kv.w;
            *(float4*)&Vs[row * 256 + c4] = *(const float4*)(kbase + 512 + c4);
        }
        __syncthreads();

        // S = Q @ K^T for 4x4 sub-tile
        float s[4][4];
        #pragma unroll
        for (int i = 0; i < 4; i++)
            #pragma unroll
            for (int j = 0; j < 4; j++) s[i][j] = 0.f;

        #pragma unroll 4
        for (int k = 0; k < 256; k++) {
            float4 qv = *(const float4*)(Qt + k * QKT_STRIDE + (ty << 2));
            float4 kv = *(const float4*)(Kt + k * QKT_STRIDE + (tx << 2));
            float qa[4] = {qv.x, qv.y, qv.z, qv.w};
            float ka[4] = {kv.x, kv.y, kv.z, kv.w};
            #pragma unroll
            for (int i = 0; i < 4; i++)
                #pragma unroll
                for (int j = 0; j < 4; j++)
                    s[i][j] += qa[i] * ka[j];
        }

        // scale + causal mask (only diagonal block needs it)
        #pragma unroll
        for (int i = 0; i < 4; i++)
            #pragma unroll
            for (int j = 0; j < 4; j++) s[i][j] *= 0.0625f;
        if (kb == qb) {
            int rb = ty << 2, cb = tx << 2;
            #pragma unroll
            for (int i = 0; i < 4; i++)
                #pragma unroll
                for (int j = 0; j < 4; j++)
                    if (cb + j > rb + i) s[i][j] = -3.0e38f;
        }

        // online softmax (row reductions across the 16 tx lanes)
        #pragma unroll
        for (int i = 0; i < 4; i++) {
            float rm = fmaxf(fmaxf(s[i][0], s[i][1]), fmaxf(s[i][2], s[i][3]));
            rm = fmaxf(rm, __shfl_xor_sync(0xffffffffu, rm, 1));
            rm = fmaxf(rm, __shfl_xor_sync(0xffffffffu, rm, 2));
            rm = fmaxf(rm, __shfl_xor_sync(0xffffffffu, rm, 4));
            rm = fmaxf(rm, __shfl_xor_sync(0xffffffffu, rm, 8));
            float mn = fmaxf(m_i[i], rm);
            float alpha = __expf(m_i[i] - mn);
            m_i[i] = mn;
            float rs = 0.f;
            #pragma unroll
            for (int j = 0; j < 4; j++) {
                s[i][j] = __expf(s[i][j] - mn);
                rs += s[i][j];
            }
            rs += __shfl_xor_sync(0xffffffffu, rs, 1);
            rs += __shfl_xor_sync(0xffffffffu, rs, 2);
            rs += __shfl_xor_sync(0xffffffffu, rs, 4);
            rs += __shfl_xor_sync(0xffffffffu, rs, 8);
            l_i[i] = l_i[i] * alpha + rs;
            #pragma unroll
            for (int j = 0; j < 16; j++) o[i][j] *= alpha;
            *(float4*)&Ps[((ty << 2) + i) * QKT_STRIDE + (tx << 2)] =
                make_float4(s[i][0], s[i][1], s[i][2], s[i][3]);
        }
        __syncthreads();

        // O += P @ V  (thread owns 4 rows x {tx*4 + 64*g} cols)
        for (int c = 0; c < 64; c++) {
            float pa[4];
            #pragma unroll
            for (int i = 0; i < 4; i++)
                pa[i] = Ps[((ty << 2) + i) * QKT_STRIDE + c];
            #pragma unroll
            for (int g = 0; g < 4; g++) {
                float4 v = *(const float4*)(Vs + c * 256 + (g << 6) + (tx << 2));
                float va[4] = {v.x, v.y, v.z, v.w};
                #pragma unroll
                for (int i = 0; i < 4; i++)
                    #pragma unroll
                    for (int w = 0; w < 4; w++)
                        o[i][(g << 2) + w] += pa[i] * va[w];
            }
        }
    }

    // epilogue: normalize and write
    #pragma unroll
    for (int i = 0; i < 4; i++) {
        float inv = 1.0f / l_i[i];
        int row = qb * 64 + (ty << 2) + i;
        float* op = outp + ((size_t)b * T_SZ + row) * D_SZ;
        #pragma unroll
        for (int g = 0; g < 4; g++) {
            float4 v = make_float4(o[i][(g << 2) + 0] * inv, o[i][(g << 2) + 1] * inv,
                                   o[i][(g << 2) + 2] * inv, o[i][(g << 2) + 3] * inv);
            *(float4*)(op + (g << 6) + (tx << 2)) = v;
        }
    }
}

// ---------------- 4) head GEMM fused with shifted-target MSE partials ----------------
// 8 tokens per block (32 threads per token: one per PS output). Deterministic partials.
__global__ __launch_bounds__(256) void head_loss_kernel(const float* __restrict__ X,
                                                        const float* __restrict__ Wh,
                                                        const float* __restrict__ bh) {
    __shared__ float Ws[256 * 32];
    __shared__ float Xs[8 * 256];
    int tid = threadIdx.x;
    int t0 = blockIdx.x * 8;
    for (int i = tid; i < 256 * 32; i += 256) Ws[i] = __ldg(&Wh[i]);
    for (int i = tid; i < 8 * 256; i += 256) Xs[i] = X[(size_t)t0 * 256 + i];
    __syncthreads();

    int li = tid >> 5, n = tid & 31;
    const float* xp = &Xs[li * 256];
    float acc = 0.f;
    #pragma unroll 8
    for (int k = 0; k < 256; k++) acc += xp[k] * Ws[k * 32 + n];
    acc += __ldg(&bh[n]);

    int tok = t0 + li;
    int b = tok >> 10, t = tok & 1023;
    float d2 = 0.f;
    if (t < T_SZ - 1) {
        float tgt = g_xn[(size_t)b * L_SZ + (t + 1) * PS_SZ + n];
        float d = acc - tgt;
        d2 = d * d;
    }
    for (int o = 16; o > 0; o >>= 1) d2 += __shfl_xor_sync(0xffffffffu, d2, o);
    __shared__ float red[8];
    if ((tid & 31) == 0) red[tid >> 5] = d2;
    __syncthreads();
    if (tid == 0) {
        float ssum = 0.f;
        #pragma unroll
        for (int i = 0; i < 8; i++) ssum += red[i];
        g_partial[blockIdx.x] = ssum;
    }
}

__global__ __launch_bounds__(256) void finalize_kernel(float* __restrict__ out) {
    __shared__ double red[256];
    double s = 0.0;
    for (int i = threadIdx.x; i < 4096; i += 256) s += (double)g_partial[i];
    red[threadIdx.x] = s;
    __syncthreads();
    for (int st = 128; st > 0; st >>= 1) {
        if (threadIdx.x < st) red[threadIdx.x] += red[threadIdx.x + st];
        __syncthreads();
    }
    if (threadIdx.x == 0)
        out[0] = (float)(red[0] / (double)((size_t)B_SZ * (T_SZ - 1) * PS_SZ));
}

// ---------------- launch ----------------
extern "C" void kernel_launch(void* const* d_in, const int* in_sizes, int n_in,
                              void* d_out, int out_size) {
    const float* x      = (const float*)d_in[0];
    const float* W_proj = (const float*)d_in[1];
    const float* b_proj = (const float*)d_in[2];
    const float* W_qkv  = (const float*)d_in[3];
    const float* b_qkv  = (const float*)d_in[4];
    const float* W_out  = (const float*)d_in[5];
    const float* b_out  = (const float*)d_in[6];
    const float* W_head = (const float*)d_in[7];
    const float* b_head = (const float*)d_in[8];

    float *xn, *h, *qkvb, *attn, *out2;
    cudaGetSymbolAddress((void**)&xn,   g_xn);
    cudaGetSymbolAddress((void**)&h,    g_h);
    cudaGetSymbolAddress((void**)&qkvb, g_qkv);
    cudaGetSymbolAddress((void**)&attn, g_attn);
    cudaGetSymbolAddress((void**)&out2, g_out2);

    cudaFuncSetAttribute(flash_kernel, cudaFuncAttributeMaxDynamicSharedMemorySize,
                         FA_SMEM);

    // 1) instance norm -> normalized patches
    norm_kernel<<<B_SZ, 1024>>>(x);
    // 2) patch embedding: [32768,32] @ [32,256] + b
    sgemm_bias<<<dim3(2, 256), 256>>>(xn, W_proj, b_proj, h, NTOK, D_SZ, PS_SZ);
    // 3) qkv: [32768,256] @ [256,768] + b
    sgemm_bias<<<dim3(6, 256), 256>>>(h, W_qkv, b_qkv, qkvb, NTOK, 3 * D_SZ, D_SZ);
    // 4) causal flash attention
    flash_kernel<<<dim3(16, B_SZ), 256, FA_SMEM>>>(qkvb, attn);
    // 5) output projection: [32768,256] @ [256,256] + b
    sgemm_bias<<<dim3(2, 256), 256>>>(attn, W_out, b_out, out2, NTOK, D_SZ, D_SZ);
    // 6) head + shifted-MSE partials, 7) deterministic finalize
    head_loss_kernel<<<NTOK / 8, 256>>>(out2, W_head, b_head);
    finalize_kernel<<<1, 256>>>((float*)d_out);
}

// round 4
// speedup vs baseline: 1.4410x; 1.4410x over previous
#include <cuda_runtime.h>
#include <cuda_bf16.h>
#include <math.h>
#include <stdint.h>

#define B_SZ 32
#define L_SZ 32768
#define PS_SZ 32
#define T_SZ 1024
#define D_SZ 256
#define NTOK (B_SZ * T_SZ)   // 32768

// ---------------- scratch (no allocs allowed; BSS device globals) ----------------
__device__ float g_xn[B_SZ * L_SZ];                 // normalized series (4 MB)
__device__ float g_h[NTOK * D_SZ];                  // patch embedding (32 MB)
__device__ __nv_bfloat16 g_qkvh[NTOK * 3 * D_SZ];   // qkv in bf16 (48 MB)
__device__ float g_attn[NTOK * D_SZ];               // attention out (32 MB)
__device__ float g_out2[NTOK * D_SZ];               // after W_out (32 MB)
__device__ float g_partial[4096];                   // per-block loss partials

// ---------------- small PTX helpers ----------------
__device__ __forceinline__ uint32_t smem_u32(const void* p) {
    uint32_t a;
    asm("{ .reg .u64 t; cvta.to.shared.u64 t, %1; cvt.u32.u64 %0, t; }"
        : "=r"(a) : "l"(p));
    return a;
}
__device__ __forceinline__ void ldsm4(uint32_t& r0, uint32_t& r1, uint32_t& r2,
                                      uint32_t& r3, uint32_t addr) {
    asm volatile("ldmatrix.sync.aligned.m8n8.x4.shared.b16 {%0,%1,%2,%3}, [%4];"
                 : "=r"(r0), "=r"(r1), "=r"(r2), "=r"(r3) : "r"(addr));
}
__device__ __forceinline__ void ldsm4t(uint32_t& r0, uint32_t& r1, uint32_t& r2,
                                       uint32_t& r3, uint32_t addr) {
    asm volatile("ldmatrix.sync.aligned.m8n8.x4.trans.shared.b16 {%0,%1,%2,%3}, [%4];"
                 : "=r"(r0), "=r"(r1), "=r"(r2), "=r"(r3) : "r"(addr));
}
__device__ __forceinline__ void mma_bf16(float* c, uint32_t a0, uint32_t a1,
                                         uint32_t a2, uint32_t a3,
                                         uint32_t b0, uint32_t b1) {
    asm volatile(
        "mma.sync.aligned.m16n8k16.row.col.f32.bf16.bf16.f32 "
        "{%0,%1,%2,%3}, {%4,%5,%6,%7}, {%8,%9}, {%0,%1,%2,%3};"
        : "+f"(c[0]), "+f"(c[1]), "+f"(c[2]), "+f"(c[3])
        : "r"(a0), "r"(a1), "r"(a2), "r"(a3), "r"(b0), "r"(b1));
}
__device__ __forceinline__ uint32_t pack_bf16(float lo, float hi) {
    uint32_t d;
    asm("cvt.rn.bf16x2.f32 %0, %1, %2;" : "=r"(d) : "f"(hi), "f"(lo));
    return d;
}

// ---------------- 1) instance norm over full series (ddof=1) ----------------
__global__ __launch_bounds__(1024) void norm_kernel(const float* __restrict__ x) {
    int b = blockIdx.x;
    const float* xr = x + (size_t)b * L_SZ;
    float s = 0.f, sq = 0.f;
    for (int i = threadIdx.x; i < L_SZ; i += 1024) {
        float v = xr[i];
        s += v; sq += v * v;
    }
    for (int o = 16; o > 0; o >>= 1) {
        s  += __shfl_xor_sync(0xffffffffu, s,  o);
        sq += __shfl_xor_sync(0xffffffffu, sq, o);
    }
    __shared__ float ss[32], ssq[32];
    __shared__ float sm_mean, sm_inv;
    int w = threadIdx.x >> 5;
    if ((threadIdx.x & 31) == 0) { ss[w] = s; ssq[w] = sq; }
    __syncthreads();
    if (threadIdx.x == 0) {
        float S = 0.f, SQ = 0.f;
        #pragma unroll
        for (int i = 0; i < 32; i++) { S += ss[i]; SQ += ssq[i]; }
        float mean = S / (float)L_SZ;
        float var = (SQ - (float)L_SZ * mean * mean) / (float)(L_SZ - 1);
        sm_mean = mean;
        sm_inv = 1.0f / (sqrtf(var) + 1e-5f);
    }
    __syncthreads();
    float mean = sm_mean, inv = sm_inv;
    float* op = g_xn + (size_t)b * L_SZ;
    for (int i = threadIdx.x; i < L_SZ; i += 1024)
        op[i] = (xr[i] - mean) * inv;
}

// ---------------- 2) generic fp32 SGEMM: C = A @ B + bias ----------------
__global__ __launch_bounds__(256) void sgemm_bias(const float* __restrict__ A,
                                                  const float* __restrict__ Bm,
                                                  const float* __restrict__ bias,
                                                  float* __restrict__ C,
                                                  int M, int N, int K) {
    __shared__ float As[8][128];
    __shared__ float Bs[8][128];
    int tid = threadIdx.x;
    int bm = blockIdx.y * 128, bn = blockIdx.x * 128;
    int arow = tid >> 1, acol = (tid & 1) << 2;
    int brow = tid >> 5, bcol = (tid & 31) << 2;
    int tr = (tid >> 4) << 3, tc = (tid & 15) << 3;

    float acc[8][8];
    #pragma unroll
    for (int i = 0; i < 8; i++)
        #pragma unroll
        for (int j = 0; j < 8; j++) acc[i][j] = 0.f;

    for (int k0 = 0; k0 < K; k0 += 8) {
        float4 a4 = *(const float4*)(A + (size_t)(bm + arow) * K + k0 + acol);
        As[acol + 0][arow] = a4.x;
        As[acol + 1][arow] = a4.y;
        As[acol + 2][arow] = a4.z;
        As[acol + 3][arow] = a4.w;
        *(float4*)&Bs[brow][bcol] =
            *(const float4*)(Bm + (size_t)(k0 + brow) * N + bn + bcol);
        __syncthreads();
        #pragma unroll
        for (int k = 0; k < 8; k++) {
            float ar[8], br[8];
            *(float4*)&ar[0] = *(float4*)&As[k][tr];
            *(float4*)&ar[4] = *(float4*)&As[k][tr + 4];
            *(float4*)&br[0] = *(float4*)&Bs[k][tc];
            *(float4*)&br[4] = *(float4*)&Bs[k][tc + 4];
            #pragma unroll
            for (int i = 0; i < 8; i++)
                #pragma unroll
                for (int j = 0; j < 8; j++)
                    acc[i][j] += ar[i] * br[j];
        }
        __syncthreads();
    }
    float bz[8];
    #pragma unroll
    for (int j = 0; j < 8; j++) bz[j] = bias[bn + tc + j];
    #pragma unroll
    for (int i = 0; i < 8; i++) {
        int row = bm + tr + i;
        float4 o0, o1;
        o0.x = acc[i][0] + bz[0]; o0.y = acc[i][1] + bz[1];
        o0.z = acc[i][2] + bz[2]; o0.w = acc[i][3] + bz[3];
        o1.x = acc[i][4] + bz[4]; o1.y = acc[i][5] + bz[5];
        o1.z = acc[i][6] + bz[6]; o1.w = acc[i][7] + bz[7];
        *(float4*)(C + (size_t)row * N + bn + tc)     = o0;
        *(float4*)(C + (size_t)row * N + bn + tc + 4) = o1;
    }
}

// ---------------- 2b) same SGEMM, bf16 output (for QKV) ----------------
__global__ __launch_bounds__(256) void sgemm_bias_bf16(const float* __restrict__ A,
                                                       const float* __restrict__ Bm,
                                                       const float* __restrict__ bias,
                                                       __nv_bfloat16* __restrict__ C,
                                                       int M, int N, int K) {
    __shared__ float As[8][128];
    __shared__ float Bs[8][128];
    int tid = threadIdx.x;
    int bm = blockIdx.y * 128, bn = blockIdx.x * 128;
    int arow = tid >> 1, acol = (tid & 1) << 2;
    int brow = tid >> 5, bcol = (tid & 31) << 2;
    int tr = (tid >> 4) << 3, tc = (tid & 15) << 3;

    float acc[8][8];
    #pragma unroll
    for (int i = 0; i < 8; i++)
        #pragma unroll
        for (int j = 0; j < 8; j++) acc[i][j] = 0.f;

    for (int k0 = 0; k0 < K; k0 += 8) {
        float4 a4 = *(const float4*)(A + (size_t)(bm + arow) * K + k0 + acol);
        As[acol + 0][arow] = a4.x;
        As[acol + 1][arow] = a4.y;
        As[acol + 2][arow] = a4.z;
        As[acol + 3][arow] = a4.w;
        *(float4*)&Bs[brow][bcol] =
            *(const float4*)(Bm + (size_t)(k0 + brow) * N + bn + bcol);
        __syncthreads();
        #pragma unroll
        for (int k = 0; k < 8; k++) {
            float ar[8], br[8];
            *(float4*)&ar[0] = *(float4*)&As[k][tr];
            *(float4*)&ar[4] = *(float4*)&As[k][tr + 4];
            *(float4*)&br[0] = *(float4*)&Bs[k][tc];
            *(float4*)&br[4] = *(float4*)&Bs[k][tc + 4];
            #pragma unroll
            for (int i = 0; i < 8; i++)
                #pragma unroll
                for (int j = 0; j < 8; j++)
                    acc[i][j] += ar[i] * br[j];
        }
        __syncthreads();
    }
    float bz[8];
    #pragma unroll
    for (int j = 0; j < 8; j++) bz[j] = bias[bn + tc + j];
    #pragma unroll
    for (int i = 0; i < 8; i++) {
        int row = bm + tr + i;
        __nv_bfloat16 tmp[8];
        #pragma unroll
        for (int j = 0; j < 8; j++)
            tmp[j] = __float2bfloat16(acc[i][j] + bz[j]);
        *(uint4*)(C + (size_t)row * N + bn + tc) = *(uint4*)tmp;
    }
}

// ---------------- 3) causal flash attention, bf16 mma.sync ----------------
// 128 threads (4 warps), each warp owns 16 q-rows of a 64-row Q block.
// smem: Qs/Ks/Vs [64][264] bf16 = 101376 B dynamic.
#define FH_STRIDE 264
#define FAM_SMEM (3 * 64 * FH_STRIDE * 2)

__global__ __launch_bounds__(128) void flash_mma_kernel(
        const __nv_bfloat16* __restrict__ qkv, float* __restrict__ outp) {
    extern __shared__ __nv_bfloat16 smb[];
    __nv_bfloat16* Qs = smb;
    __nv_bfloat16* Ks = smb + 64 * FH_STRIDE;
    __nv_bfloat16* Vs = smb + 2 * 64 * FH_STRIDE;

    int b = blockIdx.y;
    int qb = 15 - (int)blockIdx.x;     // heavy blocks scheduled first
    int tid = threadIdx.x;
    int w = tid >> 5, t = tid & 31;
    const __nv_bfloat16* base = qkv + (size_t)b * T_SZ * 768;
    const __nv_bfloat16* qbase = base + (size_t)(qb * 64) * 768;

    // load Q tile (row-major [qrow][k])
    for (int i = tid; i < 64 * 32; i += 128) {
        int row = i >> 5, c8 = (i & 31) << 3;
        *(uint4*)&Qs[row * FH_STRIDE + c8] = *(const uint4*)(qbase + row * 768 + c8);
    }

    // per-lane ldmatrix base addresses (bytes)
    int rowA = (t & 7) + ((t >> 3) & 1) * 8;           // Q / V row pattern
    uint32_t aBase = smem_u32(Qs) +
        (uint32_t)(((16 * w + rowA) * FH_STRIDE + ((t >> 4) << 3)) * 2);
    int matB = t >> 3;
    uint32_t bBase = smem_u32(Ks) +
        (uint32_t)((((t & 7) + (matB >> 1) * 8) * FH_STRIDE + ((matB & 1) << 3)) * 2);
    uint32_t vBase = smem_u32(Vs) +
        (uint32_t)((rowA * FH_STRIDE + ((t >> 4) << 3)) * 2);

    float o[32][4];
    #pragma unroll
    for (int n = 0; n < 32; n++)
        #pragma unroll
        for (int e = 0; e < 4; e++) o[n][e] = 0.f;
    float m0 = -1e30f, m1 = -1e30f, l0 = 0.f, l1 = 0.f;

    for (int kb = 0; kb <= qb; kb++) {
        __syncthreads();
        const __nv_bfloat16* kptr = base + (size_t)(kb * 64) * 768;
        for (int i = tid; i < 64 * 32; i += 128) {
            int row = i >> 5, c8 = (i & 31) << 3;
            *(uint4*)&Ks[row * FH_STRIDE + c8] =
                *(const uint4*)(kptr + row * 768 + 256 + c8);
            *(uint4*)&Vs[row * FH_STRIDE + c8] =
                *(const uint4*)(kptr + row * 768 + 512 + c8);
        }
        __syncthreads();

        // ---- S = Q @ K^T (16x64 per warp) ----
        float c[8][4];
        #pragma unroll
        for (int j = 0; j < 8; j++)
            #pragma unroll
            for (int e = 0; e < 4; e++) c[j][e] = 0.f;

        #pragma unroll
        for (int kf = 0; kf < 16; kf++) {
            uint32_t a0, a1, a2, a3;
            ldsm4(a0, a1, a2, a3, aBase + kf * 32);
            #pragma unroll
            for (int nf = 0; nf < 4; nf++) {
                uint32_t b0, b1, b2, b3;
                ldsm4(b0, b1, b2, b3,
                      bBase + nf * (16 * FH_STRIDE * 2) + kf * 32);
                mma_bf16(c[2 * nf],     a0, a1, a2, a3, b0, b1);
                mma_bf16(c[2 * nf + 1], a0, a1, a2, a3, b2, b3);
            }
        }

        // scale
        #pragma unroll
        for (int j = 0; j < 8; j++)
            #pragma unroll
            for (int e = 0; e < 4; e++) c[j][e] *= 0.0625f;

        // causal mask (diagonal tile only)
        int r0l = 16 * w + (t >> 2), r1l = r0l + 8;
        if (kb == qb) {
            #pragma unroll
            for (int j = 0; j < 8; j++) {
                int col = 8 * j + (t & 3) * 2;
                if (col     > r0l) c[j][0] = -1e30f;
                if (col + 1 > r0l) c[j][1] = -1e30f;
                if (col     > r1l) c[j][2] = -1e30f;
                if (col + 1 > r1l) c[j][3] = -1e30f;
            }
        }

        // ---- online softmax ----
        float mx0 = -1e30f, mx1 = -1e30f;
        #pragma unroll
        for (int j = 0; j < 8; j++) {
            mx0 = fmaxf(mx0, fmaxf(c[j][0], c[j][1]));
            mx1 = fmaxf(mx1, fmaxf(c[j][2], c[j][3]));
        }
        mx0 = fmaxf(mx0, __shfl_xor_sync(0xffffffffu, mx0, 1));
        mx0 = fmaxf(mx0, __shfl_xor_sync(0xffffffffu, mx0, 2));
        mx1 = fmaxf(mx1, __shfl_xor_sync(0xffffffffu, mx1, 1));
        mx1 = fmaxf(mx1, __shfl_xor_sync(0xffffffffu, mx1, 2));
        float mn0 = fmaxf(m0, mx0), mn1 = fmaxf(m1, mx1);
        float al0 = __expf(m0 - mn0), al1 = __expf(m1 - mn1);
        m0 = mn0; m1 = mn1;
        float s0 = 0.f, s1 = 0.f;
        #pragma unroll
        for (int j = 0; j < 8; j++) {
            c[j][0] = __expf(c[j][0] - mn0);
            c[j][1] = __expf(c[j][1] - mn0);
            c[j][2] = __expf(c[j][2] - mn1);
            c[j][3] = __expf(c[j][3] - mn1);
            s0 += c[j][0] + c[j][1];
            s1 += c[j][2] + c[j][3];
        }
        s0 += __shfl_xor_sync(0xffffffffu, s0, 1);
        s0 += __shfl_xor_sync(0xffffffffu, s0, 2);
        s1 += __shfl_xor_sync(0xffffffffu, s1, 1);
        s1 += __shfl_xor_sync(0xffffffffu, s1, 2);
        l0 = l0 * al0 + s0;
        l1 = l1 * al1 + s1;
        #pragma unroll
        for (int n = 0; n < 32; n++) {
            o[n][0] *= al0; o[n][1] *= al0;
            o[n][2] *= al1; o[n][3] *= al1;
        }

        // pack P fragments (S accum layout == A fragment layout)
        uint32_t p[4][4];
        #pragma unroll
        for (int f = 0; f < 4; f++) {
            p[f][0] = pack_bf16(c[2 * f][0],     c[2 * f][1]);
            p[f][1] = pack_bf16(c[2 * f][2],     c[2 * f][3]);
            p[f][2] = pack_bf16(c[2 * f + 1][0], c[2 * f + 1][1]);
            p[f][3] = pack_bf16(c[2 * f + 1][2], c[2 * f + 1][3]);
        }

        // ---- O += P @ V ----
        #pragma unroll
        for (int f = 0; f < 4; f++) {
            #pragma unroll
            for (int nf = 0; nf < 16; nf++) {
                uint32_t b0, b1, b2, b3;
                ldsm4t(b0, b1, b2, b3,
                       vBase + f * (16 * FH_STRIDE * 2) + nf * 32);
                mma_bf16(o[2 * nf],     p[f][0], p[f][1], p[f][2], p[f][3], b0, b1);
                mma_bf16(o[2 * nf + 1], p[f][0], p[f][1], p[f][2], p[f][3], b2, b3);
            }
        }
    }

    // epilogue
    float inv0 = 1.0f / l0, inv1 = 1.0f / l1;
    int gr0 = qb * 64 + 16 * w + (t >> 2);
    float* op0 = outp + ((size_t)b * T_SZ + gr0) * 256;
    float* op1 = op0 + 8 * 256;
    #pragma unroll
    for (int n = 0; n < 32; n++) {
        int col = 8 * n + (t & 3) * 2;
        *(float2*)(op0 + col) = make_float2(o[n][0] * inv0, o[n][1] * inv0);
        *(float2*)(op1 + col) = make_float2(o[n][2] * inv1, o[n][3] * inv1);
    }
}

// ---------------- 4) head GEMM fused with shifted-target MSE partials ----------------
__global__ __launch_bounds__(256) void head_loss_kernel(const float* __restrict__ X,
                                                        const float* __restrict__ Wh,
                                                        const float* __restrict__ bh) {
    __shared__ float Ws[256 * 32];
    __shared__ float Xs[8 * 256];
    int tid = threadIdx.x;
    int t0 = blockIdx.x * 8;
    for (int i = tid; i < 256 * 32; i += 256) Ws[i] = __ldg(&Wh[i]);
    for (int i = tid; i < 8 * 256; i += 256) Xs[i] = X[(size_t)t0 * 256 + i];
    __syncthreads();

    int li = tid >> 5, n = tid & 31;
    const float* xp = &Xs[li * 256];
    float acc = 0.f;
    #pragma unroll 8
    for (int k = 0; k < 256; k++) acc += xp[k] * Ws[k * 32 + n];
    acc += __ldg(&bh[n]);

    int tok = t0 + li;
    int b = tok >> 10, t = tok & 1023;
    float d2 = 0.f;
    if (t < T_SZ - 1) {
        float tgt = g_xn[(size_t)b * L_SZ + (t + 1) * PS_SZ + n];
        float d = acc - tgt;
        d2 = d * d;
    }
    for (int o = 16; o > 0; o >>= 1) d2 += __shfl_xor_sync(0xffffffffu, d2, o);
    __shared__ float red[8];
    if ((tid & 31) == 0) red[tid >> 5] = d2;
    __syncthreads();
    if (tid == 0) {
        float ssum = 0.f;
        #pragma unroll
        for (int i = 0; i < 8; i++) ssum += red[i];
        g_partial[blockIdx.x] = ssum;
    }
}

__global__ __launch_bounds__(256) void finalize_kernel(float* __restrict__ out) {
    __shared__ double red[256];
    double s = 0.0;
    for (int i = threadIdx.x; i < 4096; i += 256) s += (double)g_partial[i];
    red[threadIdx.x] = s;
    __syncthreads();
    for (int st = 128; st > 0; st >>= 1) {
        if (threadIdx.x < st) red[threadIdx.x] += red[threadIdx.x + st];
        __syncthreads();
    }
    if (threadIdx.x == 0)
        out[0] = (float)(red[0] / (double)((size_t)B_SZ * (T_SZ - 1) * PS_SZ));
}

// ---------------- launch ----------------
extern "C" void kernel_launch(void* const* d_in, const int* in_sizes, int n_in,
                              void* d_out, int out_size) {
    const float* x      = (const float*)d_in[0];
    const float* W_proj = (const float*)d_in[1];
    const float* b_proj = (const float*)d_in[2];
    const float* W_qkv  = (const float*)d_in[3];
    const float* b_qkv  = (const float*)d_in[4];
    const float* W_out  = (const float*)d_in[5];
    const float* b_out  = (const float*)d_in[6];
    const float* W_head = (const float*)d_in[7];
    const float* b_head = (const float*)d_in[8];

    float *xn, *h, *attn, *out2;
    __nv_bfloat16* qkvh;
    cudaGetSymbolAddress((void**)&xn,   g_xn);
    cudaGetSymbolAddress((void**)&h,    g_h);
    cudaGetSymbolAddress((void**)&qkvh, g_qkvh);
    cudaGetSymbolAddress((void**)&attn, g_attn);
    cudaGetSymbolAddress((void**)&out2, g_out2);

    cudaFuncSetAttribute(flash_mma_kernel,
                         cudaFuncAttributeMaxDynamicSharedMemorySize, FAM_SMEM);

    // 1) instance norm
    norm_kernel<<<B_SZ, 1024>>>(x);
    // 2) patch embedding: [32768,32] @ [32,256] + b
    sgemm_bias<<<dim3(2, 256), 256>>>(xn, W_proj, b_proj, h, NTOK, D_SZ, PS_SZ);
    // 3) qkv: [32768,256] @ [256,768] + b  -> bf16
    sgemm_bias_bf16<<<dim3(6, 256), 256>>>(h, W_qkv, b_qkv, qkvh, NTOK, 3 * D_SZ, D_SZ);
    // 4) causal flash attention (bf16 tensor cores, fp32 accumulate)
    flash_mma_kernel<<<dim3(16, B_SZ), 128, FAM_SMEM>>>(qkvh, attn);
    // 5) output projection: [32768,256] @ [256,256] + b
    sgemm_bias<<<dim3(2, 256), 256>>>(attn, W_out, b_out, out2, NTOK, D_SZ, D_SZ);
    // 6) head + shifted-MSE partials, 7) deterministic finalize
    head_loss_kernel<<<NTOK / 8, 256>>>(out2, W_head, b_head);
    finalize_kernel<<<1, 256>>>((float*)d_out);
}

// round 5
// speedup vs baseline: 4.8280x; 3.3504x over previous
#include <cuda_runtime.h>
#include <cuda_bf16.h>
#include <math.h>
#include <stdint.h>

#define B_SZ 32
#define L_SZ 32768
#define PS_SZ 32
#define T_SZ 1024
#define D_SZ 256
#define NTOK (B_SZ * T_SZ)   // 32768

// ---------------- scratch (no allocs allowed; BSS device globals) ----------------
__device__ float g_xn[B_SZ * L_SZ];                  // normalized series fp32 (loss target)
__device__ __nv_bfloat16 g_xnh[B_SZ * L_SZ];         // normalized series bf16 (embed input)
__device__ __nv_bfloat16 g_hh[NTOK * D_SZ];          // patch embedding bf16
__device__ __nv_bfloat16 g_qkvh[NTOK * 3 * D_SZ];    // qkv bf16
__device__ __nv_bfloat16 g_attnh[NTOK * D_SZ];       // attention out bf16
__device__ __nv_bfloat16 g_out2h[NTOK * D_SZ];       // after W_out bf16
__device__ __nv_bfloat16 g_Wp[PS_SZ * D_SZ];         // W_proj bf16
__device__ __nv_bfloat16 g_Wq[D_SZ * 3 * D_SZ];      // W_qkv bf16
__device__ __nv_bfloat16 g_Wo[D_SZ * D_SZ];          // W_out bf16
__device__ float g_partial[4096];                    // per-block loss partials

// ---------------- small PTX helpers ----------------
__device__ __forceinline__ uint32_t smem_u32(const void* p) {
    uint32_t a;
    asm("{ .reg .u64 t; cvta.to.shared.u64 t, %1; cvt.u32.u64 %0, t; }"
        : "=r"(a) : "l"(p));
    return a;
}
__device__ __forceinline__ void ldsm4(uint32_t& r0, uint32_t& r1, uint32_t& r2,
                                      uint32_t& r3, uint32_t addr) {
    asm volatile("ldmatrix.sync.aligned.m8n8.x4.shared.b16 {%0,%1,%2,%3}, [%4];"
                 : "=r"(r0), "=r"(r1), "=r"(r2), "=r"(r3) : "r"(addr));
}
__device__ __forceinline__ void ldsm4t(uint32_t& r0, uint32_t& r1, uint32_t& r2,
                                       uint32_t& r3, uint32_t addr) {
    asm volatile("ldmatrix.sync.aligned.m8n8.x4.trans.shared.b16 {%0,%1,%2,%3}, [%4];"
                 : "=r"(r0), "=r"(r1), "=r"(r2), "=r"(r3) : "r"(addr));
}
__device__ __forceinline__ void mma_bf16(float* c, uint32_t a0, uint32_t a1,
                                         uint32_t a2, uint32_t a3,
                                         uint32_t b0, uint32_t b1) {
    asm volatile(
        "mma.sync.aligned.m16n8k16.row.col.f32.bf16.bf16.f32 "
        "{%0,%1,%2,%3}, {%4,%5,%6,%7}, {%8,%9}, {%0,%1,%2,%3};"
        : "+f"(c[0]), "+f"(c[1]), "+f"(c[2]), "+f"(c[3])
        : "r"(a0), "r"(a1), "r"(a2), "r"(a3), "r"(b0), "r"(b1));
}
__device__ __forceinline__ uint32_t pack_bf16(float lo, float hi) {
    uint32_t d;
    asm("cvt.rn.bf16x2.f32 %0, %1, %2;" : "=r"(d) : "f"(hi), "f"(lo));
    return d;
}

// ---------------- 0) fp32 -> bf16 weight conversion ----------------
__global__ void cvt_f2b(const float* __restrict__ src, __nv_bfloat16* __restrict__ dst,
                        int n) {
    int i = (blockIdx.x * 256 + threadIdx.x) * 4;
    if (i < n) {
        float4 v = *(const float4*)(src + i);
        __nv_bfloat16 t[4] = {__float2bfloat16(v.x), __float2bfloat16(v.y),
                              __float2bfloat16(v.z), __float2bfloat16(v.w)};
        *(uint2*)(dst + i) = *(uint2*)t;
    }
}

// ---------------- 1) instance norm over full series (ddof=1) ----------------
__global__ __launch_bounds__(1024) void norm_kernel(const float* __restrict__ x) {
    int b = blockIdx.x;
    const float* xr = x + (size_t)b * L_SZ;
    float s = 0.f, sq = 0.f;
    for (int i = threadIdx.x; i < L_SZ; i += 1024) {
        float v = xr[i];
        s += v; sq += v * v;
    }
    for (int o = 16; o > 0; o >>= 1) {
        s  += __shfl_xor_sync(0xffffffffu, s,  o);
        sq += __shfl_xor_sync(0xffffffffu, sq, o);
    }
    __shared__ float ss[32], ssq[32];
    __shared__ float sm_mean, sm_inv;
    int w = threadIdx.x >> 5;
    if ((threadIdx.x & 31) == 0) { ss[w] = s; ssq[w] = sq; }
    __syncthreads();
    if (threadIdx.x == 0) {
        float S = 0.f, SQ = 0.f;
        #pragma unroll
        for (int i = 0; i < 32; i++) { S += ss[i]; SQ += ssq[i]; }
        float mean = S / (float)L_SZ;
        float var = (SQ - (float)L_SZ * mean * mean) / (float)(L_SZ - 1);
        sm_mean = mean;
        sm_inv = 1.0f / (sqrtf(var) + 1e-5f);
    }
    __syncthreads();
    float mean = sm_mean, inv = sm_inv;
    float* op = g_xn + (size_t)b * L_SZ;
    __nv_bfloat16* oph = g_xnh + (size_t)b * L_SZ;
    for (int i = threadIdx.x; i < L_SZ; i += 1024) {
        float v = (xr[i] - mean) * inv;
        op[i] = v;
        oph[i] = __float2bfloat16(v);
    }
}

// ---------------- 2) bf16 tensor-core GEMM: C[M,N] = A[M,K] @ B[K,N] + bias ----------
// 128x128 tile, BK=32, 256 threads (8 warps, each 32x64). bf16 in/out, fp32 accum.
#define AS_STRIDE 40
#define BS_STRIDE 136

__global__ __launch_bounds__(256) void hgemm_bias_bf16(
        const __nv_bfloat16* __restrict__ A, const __nv_bfloat16* __restrict__ Bm,
        const float* __restrict__ bias, __nv_bfloat16* __restrict__ C,
        int M, int N, int K) {
    __shared__ __nv_bfloat16 As[128 * AS_STRIDE];
    __shared__ __nv_bfloat16 Bs[32 * BS_STRIDE];
    int tid = threadIdx.x, w = tid >> 5, t = tid & 31;
    int bm = blockIdx.y * 128, bn = blockIdx.x * 128;
    int wm = (w & 3) * 32, wn = (w >> 2) * 64;

    int rowA = (t & 7) + ((t >> 3) & 1) * 8;
    uint32_t aBase = smem_u32(As) +
        (uint32_t)(((wm + rowA) * AS_STRIDE + ((t >> 4) << 3)) * 2);
    uint32_t bBase = smem_u32(Bs) +
        (uint32_t)((rowA * BS_STRIDE + wn + ((t >> 4) << 3)) * 2);

    float c[2][8][4];
    #pragma unroll
    for (int mi = 0; mi < 2; mi++)
        #pragma unroll
        for (int nj = 0; nj < 8; nj++)
            #pragma unroll
            for (int e = 0; e < 4; e++) c[mi][nj][e] = 0.f;

    for (int k0 = 0; k0 < K; k0 += 32) {
        // A tile: 128x32 bf16 (512 uint4, 2/thread)
        #pragma unroll
        for (int p = 0; p < 2; p++) {
            int i = tid + p * 256;
            int r = i >> 2, cc = (i & 3) << 3;
            *(uint4*)&As[r * AS_STRIDE + cc] =
                *(const uint4*)(A + (size_t)(bm + r) * K + k0 + cc);
        }
        // B tile: 32x128 bf16
        #pragma unroll
        for (int p = 0; p < 2; p++) {
            int i = tid + p * 256;
            int r = i >> 4, cc = (i & 15) << 3;
            *(uint4*)&Bs[r * BS_STRIDE + cc] =
                *(const uint4*)(Bm + (size_t)(k0 + r) * N + bn + cc);
        }
        __syncthreads();
        #pragma unroll
        for (int kf = 0; kf < 2; kf++) {
            uint32_t a0[2], a1[2], a2[2], a3[2];
            #pragma unroll
            for (int mi = 0; mi < 2; mi++)
                ldsm4(a0[mi], a1[mi], a2[mi], a3[mi],
                      aBase + mi * (16 * AS_STRIDE * 2) + kf * 32);
            #pragma unroll
            for (int nf = 0; nf < 4; nf++) {
                uint32_t b0, b1, b2, b3;
                ldsm4t(b0, b1, b2, b3,
                       bBase + kf * (16 * BS_STRIDE * 2) + nf * 32);
                #pragma unroll
                for (int mi = 0; mi < 2; mi++) {
                    mma_bf16(c[mi][2 * nf],     a0[mi], a1[mi], a2[mi], a3[mi], b0, b1);
                    mma_bf16(c[mi][2 * nf + 1], a0[mi], a1[mi], a2[mi], a3[mi], b2, b3);
                }
            }
        }
        __syncthreads();
    }

    // epilogue: add bias (fp32), pack bf16 pairs
    #pragma unroll
    for (int nj = 0; nj < 8; nj++) {
        int cb = bn + wn + nj * 8 + (t & 3) * 2;
        float bz0 = bias[cb], bz1 = bias[cb + 1];
        #pragma unroll
        for (int mi = 0; mi < 2; mi++) {
            int r0 = bm + wm + mi * 16 + (t >> 2);
            *(uint32_t*)(C + (size_t)r0 * N + cb) =
                pack_bf16(c[mi][nj][0] + bz0, c[mi][nj][1] + bz1);
            *(uint32_t*)(C + (size_t)(r0 + 8) * N + cb) =
                pack_bf16(c[mi][nj][2] + bz0, c[mi][nj][3] + bz1);
        }
    }
}

// ---------------- 3) causal flash attention, bf16 mma.sync ----------------
// 128 threads (4 warps), each warp owns 16 q-rows of a 64-row Q block.
#define FH_STRIDE 264
#define FAM_SMEM (3 * 64 * FH_STRIDE * 2)

__global__ __launch_bounds__(128) void flash_mma_kernel(
        const __nv_bfloat16* __restrict__ qkv, __nv_bfloat16* __restrict__ outp) {
    extern __shared__ __nv_bfloat16 smb[];
    __nv_bfloat16* Qs = smb;
    __nv_bfloat16* Ks = smb + 64 * FH_STRIDE;
    __nv_bfloat16* Vs = smb + 2 * 64 * FH_STRIDE;

    int b = blockIdx.y;
    int qb = 15 - (int)blockIdx.x;     // heavy blocks scheduled first
    int tid = threadIdx.x;
    int w = tid >> 5, t = tid & 31;
    const __nv_bfloat16* base = qkv + (size_t)b * T_SZ * 768;
    const __nv_bfloat16* qbase = base + (size_t)(qb * 64) * 768;

    for (int i = tid; i < 64 * 32; i += 128) {
        int row = i >> 5, c8 = (i & 31) << 3;
        *(uint4*)&Qs[row * FH_STRIDE + c8] = *(const uint4*)(qbase + row * 768 + c8);
    }

    int rowA = (t & 7) + ((t >> 3) & 1) * 8;
    uint32_t aBase = smem_u32(Qs) +
        (uint32_t)(((16 * w + rowA) * FH_STRIDE + ((t >> 4) << 3)) * 2);
    int matB = t >> 3;
    uint32_t bBase = smem_u32(Ks) +
        (uint32_t)((((t & 7) + (matB >> 1) * 8) * FH_STRIDE + ((matB & 1) << 3)) * 2);
    uint32_t vBase = smem_u32(Vs) +
        (uint32_t)((rowA * FH_STRIDE + ((t >> 4) << 3)) * 2);

    float o[32][4];
    #pragma unroll
    for (int n = 0; n < 32; n++)
        #pragma unroll
        for (int e = 0; e < 4; e++) o[n][e] = 0.f;
    float m0 = -1e30f, m1 = -1e30f, l0 = 0.f, l1 = 0.f;

    for (int kb = 0; kb <= qb; kb++) {
        __syncthreads();
        const __nv_bfloat16* kptr = base + (size_t)(kb * 64) * 768;
        for (int i = tid; i < 64 * 32; i += 128) {
            int row = i >> 5, c8 = (i & 31) << 3;
            *(uint4*)&Ks[row * FH_STRIDE + c8] =
                *(const uint4*)(kptr + row * 768 + 256 + c8);
            *(uint4*)&Vs[row * FH_STRIDE + c8] =
                *(const uint4*)(kptr + row * 768 + 512 + c8);
        }
        __syncthreads();

        float c[8][4];
        #pragma unroll
        for (int j = 0; j < 8; j++)
            #pragma unroll
            for (int e = 0; e < 4; e++) c[j][e] = 0.f;

        #pragma unroll
        for (int kf = 0; kf < 16; kf++) {
            uint32_t a0, a1, a2, a3;
            ldsm4(a0, a1, a2, a3, aBase + kf * 32);
            #pragma unroll
            for (int nf = 0; nf < 4; nf++) {
                uint32_t b0, b1, b2, b3;
                ldsm4(b0, b1, b2, b3,
                      bBase + nf * (16 * FH_STRIDE * 2) + kf * 32);
                mma_bf16(c[2 * nf],     a0, a1, a2, a3, b0, b1);
                mma_bf16(c[2 * nf + 1], a0, a1, a2, a3, b2, b3);
            }
        }

        #pragma unroll
        for (int j = 0; j < 8; j++)
            #pragma unroll
            for (int e = 0; e < 4; e++) c[j][e] *= 0.0625f;

        int r0l = 16 * w + (t >> 2), r1l = r0l + 8;
        if (kb == qb) {
            #pragma unroll
            for (int j = 0; j < 8; j++) {
                int col = 8 * j + (t & 3) * 2;
                if (col     > r0l) c[j][0] = -1e30f;
                if (col + 1 > r0l) c[j][1] = -1e30f;
                if (col     > r1l) c[j][2] = -1e30f;
                if (col + 1 > r1l) c[j][3] = -1e30f;
            }
        }

        float mx0 = -1e30f, mx1 = -1e30f;
        #pragma unroll
        for (int j = 0; j < 8; j++) {
            mx0 = fmaxf(mx0, fmaxf(c[j][0], c[j][1]));
            mx1 = fmaxf(mx1, fmaxf(c[j][2], c[j][3]));
        }
        mx0 = fmaxf(mx0, __shfl_xor_sync(0xffffffffu, mx0, 1));
        mx0 = fmaxf(mx0, __shfl_xor_sync(0xffffffffu, mx0, 2));
        mx1 = fmaxf(mx1, __shfl_xor_sync(0xffffffffu, mx1, 1));
        mx1 = fmaxf(mx1, __shfl_xor_sync(0xffffffffu, mx1, 2));
        float mn0 = fmaxf(m0, mx0), mn1 = fmaxf(m1, mx1);
        float al0 = __expf(m0 - mn0), al1 = __expf(m1 - mn1);
        m0 = mn0; m1 = mn1;
        float s0 = 0.f, s1 = 0.f;
        #pragma unroll
        for (int j = 0; j < 8; j++) {
            c[j][0] = __expf(c[j][0] - mn0);
            c[j][1] = __expf(c[j][1] - mn0);
            c[j][2] = __expf(c[j][2] - mn1);
            c[j][3] = __expf(c[j][3] - mn1);
            s0 += c[j][0] + c[j][1];
            s1 += c[j][2] + c[j][3];
        }
        s0 += __shfl_xor_sync(0xffffffffu, s0, 1);
        s0 += __shfl_xor_sync(0xffffffffu, s0, 2);
        s1 += __shfl_xor_sync(0xffffffffu, s1, 1);
        s1 += __shfl_xor_sync(0xffffffffu, s1, 2);
        l0 = l0 * al0 + s0;
        l1 = l1 * al1 + s1;
        #pragma unroll
        for (int n = 0; n < 32; n++) {
            o[n][0] *= al0; o[n][1] *= al0;
            o[n][2] *= al1; o[n][3] *= al1;
        }

        uint32_t p[4][4];
        #pragma unroll
        for (int f = 0; f < 4; f++) {
            p[f][0] = pack_bf16(c[2 * f][0],     c[2 * f][1]);
            p[f][1] = pack_bf16(c[2 * f][2],     c[2 * f][3]);
            p[f][2] = pack_bf16(c[2 * f + 1][0], c[2 * f + 1][1]);
            p[f][3] = pack_bf16(c[2 * f + 1][2], c[2 * f + 1][3]);
        }

        #pragma unroll
        for (int f = 0; f < 4; f++) {
            #pragma unroll
            for (int nf = 0; nf < 16; nf++) {
                uint32_t b0, b1, b2, b3;
                ldsm4t(b0, b1, b2, b3,
                       vBase + f * (16 * FH_STRIDE * 2) + nf * 32);
                mma_bf16(o[2 * nf],     p[f][0], p[f][1], p[f][2], p[f][3], b0, b1);
                mma_bf16(o[2 * nf + 1], p[f][0], p[f][1], p[f][2], p[f][3], b2, b3);
            }
        }
    }

    float inv0 = 1.0f / l0, inv1 = 1.0f / l1;
    int gr0 = qb * 64 + 16 * w + (t >> 2);
    __nv_bfloat16* op0 = outp + ((size_t)b * T_SZ + gr0) * 256;
    __nv_bfloat16* op1 = op0 + 8 * 256;
    #pragma unroll
    for (int n = 0; n < 32; n++) {
        int col = 8 * n + (t & 3) * 2;
        *(uint32_t*)(op0 + col) = pack_bf16(o[n][0] * inv0, o[n][1] * inv0);
        *(uint32_t*)(op1 + col) = pack_bf16(o[n][2] * inv1, o[n][3] * inv1);
    }
}

// ---------------- 4) head GEMM fused with shifted-target MSE partials ----------------
__global__ __launch_bounds__(256) void head_loss_kernel(
        const __nv_bfloat16* __restrict__ X, const float* __restrict__ Wh,
        const float* __restrict__ bh) {
    __shared__ float Ws[256 * 32];
    __shared__ float Xs[8 * 256];
    int tid = threadIdx.x;
    int t0 = blockIdx.x * 8;
    for (int i = tid; i < 256 * 32; i += 256) Ws[i] = __ldg(&Wh[i]);
    for (int i = tid; i < 8 * 256; i += 256)
        Xs[i] = __bfloat162float(X[(size_t)t0 * 256 + i]);
    __syncthreads();

    int li = tid >> 5, n = tid & 31;
    const float* xp = &Xs[li * 256];
    float acc = 0.f;
    #pragma unroll 8
    for (int k = 0; k < 256; k++) acc += xp[k] * Ws[k * 32 + n];
    acc += __ldg(&bh[n]);

    int tok = t0 + li;
    int b = tok >> 10, t = tok & 1023;
    float d2 = 0.f;
    if (t < T_SZ - 1) {
        float tgt = g_xn[(size_t)b * L_SZ + (t + 1) * PS_SZ + n];
        float d = acc - tgt;
        d2 = d * d;
    }
    for (int o = 16; o > 0; o >>= 1) d2 += __shfl_xor_sync(0xffffffffu, d2, o);
    __shared__ float red[8];
    if ((tid & 31) == 0) red[tid >> 5] = d2;
    __syncthreads();
    if (tid == 0) {
        float ssum = 0.f;
        #pragma unroll
        for (int i = 0; i < 8; i++) ssum += red[i];
        g_partial[blockIdx.x] = ssum;
    }
}

__global__ __launch_bounds__(256) void finalize_kernel(float* __restrict__ out) {
    __shared__ double red[256];
    double s = 0.0;
    for (int i = threadIdx.x; i < 4096; i += 256) s += (double)g_partial[i];
    red[threadIdx.x] = s;
    __syncthreads();
    for (int st = 128; st > 0; st >>= 1) {
        if (threadIdx.x < st) red[threadIdx.x] += red[threadIdx.x + st];
        __syncthreads();
    }
    if (threadIdx.x == 0)
        out[0] = (float)(red[0] / (double)((size_t)B_SZ * (T_SZ - 1) * PS_SZ));
}

// ---------------- launch ----------------
extern "C" void kernel_launch(void* const* d_in, const int* in_sizes, int n_in,
                              void* d_out, int out_size) {
    const float* x      = (const float*)d_in[0];
    const float* W_proj = (const float*)d_in[1];
    const float* b_proj = (const float*)d_in[2];
    const float* W_qkv  = (const float*)d_in[3];
    const float* b_qkv  = (const float*)d_in[4];
    const float* W_out  = (const float*)d_in[5];
    const float* b_out  = (const float*)d_in[6];
    const float* W_head = (const float*)d_in[7];
    const float* b_head = (const float*)d_in[8];

    __nv_bfloat16 *xnh, *hh, *qkvh, *attnh, *out2h, *Wp, *Wq, *Wo;
    cudaGetSymbolAddress((void**)&xnh,   g_xnh);
    cudaGetSymbolAddress((void**)&hh,    g_hh);
    cudaGetSymbolAddress((void**)&qkvh,  g_qkvh);
    cudaGetSymbolAddress((void**)&attnh, g_attnh);
    cudaGetSymbolAddress((void**)&out2h, g_out2h);
    cudaGetSymbolAddress((void**)&Wp,    g_Wp);
    cudaGetSymbolAddress((void**)&Wq,    g_Wq);
    cudaGetSymbolAddress((void**)&Wo,    g_Wo);

    cudaFuncSetAttribute(flash_mma_kernel,
                         cudaFuncAttributeMaxDynamicSharedMemorySize, FAM_SMEM);

    // 0) weight conversions
    cvt_f2b<<<(PS_SZ * D_SZ / 4 + 255) / 256, 256>>>(W_proj, Wp, PS_SZ * D_SZ);
    cvt_f2b<<<(D_SZ * 3 * D_SZ / 4 + 255) / 256, 256>>>(W_qkv, Wq, D_SZ * 3 * D_SZ);
    cvt_f2b<<<(D_SZ * D_SZ / 4 + 255) / 256, 256>>>(W_out, Wo, D_SZ * D_SZ);
    // 1) instance norm (fp32 target + bf16 embed input)
    norm_kernel<<<B_SZ, 1024>>>(x);
    // 2) patch embedding: [32768,32] @ [32,256] + b  (bf16 mma)
    hgemm_bias_bf16<<<dim3(2, 256), 256>>>(xnh, Wp, b_proj, hh, NTOK, D_SZ, PS_SZ);
    // 3) qkv: [32768,256] @ [256,768] + b  (bf16 mma)
    hgemm_bias_bf16<<<dim3(6, 256), 256>>>(hh, Wq, b_qkv, qkvh, NTOK, 3 * D_SZ, D_SZ);
    // 4) causal flash attention (bf16 tensor cores, fp32 accumulate)
    flash_mma_kernel<<<dim3(16, B_SZ), 128, FAM_SMEM>>>(qkvh, attnh);
    // 5) output projection: [32768,256] @ [256,256] + b  (bf16 mma)
    hgemm_bias_bf16<<<dim3(2, 256), 256>>>(attnh, Wo, b_out, out2h, NTOK, D_SZ, D_SZ);
    // 6) head + shifted-MSE partials, 7) deterministic finalize
    head_loss_kernel<<<NTOK / 8, 256>>>(out2h, W_head, b_head);
    finalize_kernel<<<1, 256>>>((float*)d_out);
}

// round 6
// speedup vs baseline: 6.2653x; 1.2977x over previous
#include <cuda_runtime.h>
#include <cuda_bf16.h>
#include <math.h>
#include <stdint.h>

#define B_SZ 32
#define L_SZ 32768
#define PS_SZ 32
#define T_SZ 1024
#define D_SZ 256
#define NTOK (B_SZ * T_SZ)   // 32768

// ---------------- scratch (no allocs allowed; BSS device globals) ----------------
__device__ float g_xn[B_SZ * L_SZ];                  // normalized series fp32 (loss target)
__device__ __nv_bfloat16 g_xnh[B_SZ * L_SZ];         // normalized series bf16 (embed input)
__device__ __nv_bfloat16 g_hh[NTOK * D_SZ];          // patch embedding bf16
__device__ __nv_bfloat16 g_qkvh[NTOK * 3 * D_SZ];    // qkv bf16
__device__ __nv_bfloat16 g_attnh[NTOK * D_SZ];       // attention out bf16
__device__ __nv_bfloat16 g_out2h[NTOK * D_SZ];       // after W_out bf16
__device__ __nv_bfloat16 g_Wp[PS_SZ * D_SZ];         // W_proj bf16
__device__ __nv_bfloat16 g_Wq[D_SZ * 3 * D_SZ];      // W_qkv bf16
__device__ __nv_bfloat16 g_Wo[D_SZ * D_SZ];          // W_out bf16
__device__ __nv_bfloat16 g_Wh[D_SZ * PS_SZ];         // W_head bf16
__device__ float g_partial[4096];                    // per-block loss partials

// ---------------- small PTX helpers ----------------
__device__ __forceinline__ uint32_t smem_u32(const void* p) {
    uint32_t a;
    asm("{ .reg .u64 t; cvta.to.shared.u64 t, %1; cvt.u32.u64 %0, t; }"
        : "=r"(a) : "l"(p));
    return a;
}
__device__ __forceinline__ void ldsm4(uint32_t& r0, uint32_t& r1, uint32_t& r2,
                                      uint32_t& r3, uint32_t addr) {
    asm volatile("ldmatrix.sync.aligned.m8n8.x4.shared.b16 {%0,%1,%2,%3}, [%4];"
                 : "=r"(r0), "=r"(r1), "=r"(r2), "=r"(r3) : "r"(addr));
}
__device__ __forceinline__ void ldsm4t(uint32_t& r0, uint32_t& r1, uint32_t& r2,
                                       uint32_t& r3, uint32_t addr) {
    asm volatile("ldmatrix.sync.aligned.m8n8.x4.trans.shared.b16 {%0,%1,%2,%3}, [%4];"
                 : "=r"(r0), "=r"(r1), "=r"(r2), "=r"(r3) : "r"(addr));
}
__device__ __forceinline__ void mma_bf16(float* c, uint32_t a0, uint32_t a1,
                                         uint32_t a2, uint32_t a3,
                                         uint32_t b0, uint32_t b1) {
    asm volatile(
        "mma.sync.aligned.m16n8k16.row.col.f32.bf16.bf16.f32 "
        "{%0,%1,%2,%3}, {%4,%5,%6,%7}, {%8,%9}, {%0,%1,%2,%3};"
        : "+f"(c[0]), "+f"(c[1]), "+f"(c[2]), "+f"(c[3])
        : "r"(a0), "r"(a1), "r"(a2), "r"(a3), "r"(b0), "r"(b1));
}
__device__ __forceinline__ uint32_t pack_bf16(float lo, float hi) {
    uint32_t d;
    asm("cvt.rn.bf16x2.f32 %0, %1, %2;" : "=r"(d) : "f"(hi), "f"(lo));
    return d;
}
__device__ __forceinline__ void cp16(uint32_t saddr, const void* gaddr) {
    asm volatile("cp.async.cg.shared.global [%0], [%1], 16;"
                 :: "r"(saddr), "l"(gaddr));
}

// ---------------- 0) fp32 -> bf16 weight conversion ----------------
__global__ void cvt_f2b(const float* __restrict__ src, __nv_bfloat16* __restrict__ dst,
                        int n) {
    int i = (blockIdx.x * 256 + threadIdx.x) * 4;
    if (i < n) {
        float4 v = *(const float4*)(src + i);
        __nv_bfloat16 t[4] = {__float2bfloat16(v.x), __float2bfloat16(v.y),
                              __float2bfloat16(v.z), __float2bfloat16(v.w)};
        *(uint2*)(dst + i) = *(uint2*)t;
    }
}

// ---------------- 1) instance norm over full series (ddof=1) ----------------
__global__ __launch_bounds__(1024) void norm_kernel(const float* __restrict__ x) {
    int b = blockIdx.x;
    const float* xr = x + (size_t)b * L_SZ;
    float s = 0.f, sq = 0.f;
    for (int i = threadIdx.x; i < L_SZ; i += 1024) {
        float v = xr[i];
        s += v; sq += v * v;
    }
    for (int o = 16; o > 0; o >>= 1) {
        s  += __shfl_xor_sync(0xffffffffu, s,  o);
        sq += __shfl_xor_sync(0xffffffffu, sq, o);
    }
    __shared__ float ss[32], ssq[32];
    __shared__ float sm_mean, sm_inv;
    int w = threadIdx.x >> 5;
    if ((threadIdx.x & 31) == 0) { ss[w] = s; ssq[w] = sq; }
    __syncthreads();
    if (threadIdx.x == 0) {
        float S = 0.f, SQ = 0.f;
        #pragma unroll
        for (int i = 0; i < 32; i++) { S += ss[i]; SQ += ssq[i]; }
        float mean = S / (float)L_SZ;
        float var = (SQ - (float)L_SZ * mean * mean) / (float)(L_SZ - 1);
        sm_mean = mean;
        sm_inv = 1.0f / (sqrtf(var) + 1e-5f);
    }
    __syncthreads();
    float mean = sm_mean, inv = sm_inv;
    float* op = g_xn + (size_t)b * L_SZ;
    __nv_bfloat16* oph = g_xnh + (size_t)b * L_SZ;
    for (int i = threadIdx.x; i < L_SZ; i += 1024) {
        float v = (xr[i] - mean) * inv;
        op[i] = v;
        oph[i] = __float2bfloat16(v);
    }
}

// ---------------- 2) bf16 tensor-core GEMM: C[M,N] = A[M,K] @ B[K,N] + bias ----------
#define AS_STRIDE 40
#define BS_STRIDE 136

__global__ __launch_bounds__(256) void hgemm_bias_bf16(
        const __nv_bfloat16* __restrict__ A, const __nv_bfloat16* __restrict__ Bm,
        const float* __restrict__ bias, __nv_bfloat16* __restrict__ C,
        int M, int N, int K) {
    __shared__ __nv_bfloat16 As[128 * AS_STRIDE];
    __shared__ __nv_bfloat16 Bs[32 * BS_STRIDE];
    int tid = threadIdx.x, w = tid >> 5, t = tid & 31;
    int bm = blockIdx.y * 128, bn = blockIdx.x * 128;
    int wm = (w & 3) * 32, wn = (w >> 2) * 64;

    int rowA = (t & 7) + ((t >> 3) & 1) * 8;
    uint32_t aBase = smem_u32(As) +
        (uint32_t)(((wm + rowA) * AS_STRIDE + ((t >> 4) << 3)) * 2);
    uint32_t bBase = smem_u32(Bs) +
        (uint32_t)((rowA * BS_STRIDE + wn + ((t >> 4) << 3)) * 2);

    float c[2][8][4];
    #pragma unroll
    for (int mi = 0; mi < 2; mi++)
        #pragma unroll
        for (int nj = 0; nj < 8; nj++)
            #pragma unroll
            for (int e = 0; e < 4; e++) c[mi][nj][e] = 0.f;

    for (int k0 = 0; k0 < K; k0 += 32) {
        #pragma unroll
        for (int p = 0; p < 2; p++) {
            int i = tid + p * 256;
            int r = i >> 2, cc = (i & 3) << 3;
            *(uint4*)&As[r * AS_STRIDE + cc] =
                *(const uint4*)(A + (size_t)(bm + r) * K + k0 + cc);
        }
        #pragma unroll
        for (int p = 0; p < 2; p++) {
            int i = tid + p * 256;
            int r = i >> 4, cc = (i & 15) << 3;
            *(uint4*)&Bs[r * BS_STRIDE + cc] =
                *(const uint4*)(Bm + (size_t)(k0 + r) * N + bn + cc);
        }
        __syncthreads();
        #pragma unroll
        for (int kf = 0; kf < 2; kf++) {
            uint32_t a0[2], a1[2], a2[2], a3[2];
            #pragma unroll
            for (int mi = 0; mi < 2; mi++)
                ldsm4(a0[mi], a1[mi], a2[mi], a3[mi],
                      aBase + mi * (16 * AS_STRIDE * 2) + kf * 32);
            #pragma unroll
            for (int nf = 0; nf < 4; nf++) {
                uint32_t b0, b1, b2, b3;
                ldsm4t(b0, b1, b2, b3,
                       bBase + kf * (16 * BS_STRIDE * 2) + nf * 32);
                #pragma unroll
                for (int mi = 0; mi < 2; mi++) {
                    mma_bf16(c[mi][2 * nf],     a0[mi], a1[mi], a2[mi], a3[mi], b0, b1);
                    mma_bf16(c[mi][2 * nf + 1], a0[mi], a1[mi], a2[mi], a3[mi], b2, b3);
                }
            }
        }
        __syncthreads();
    }

    #pragma unroll
    for (int nj = 0; nj < 8; nj++) {
        int cb = bn + wn + nj * 8 + (t & 3) * 2;
        float bz0 = bias[cb], bz1 = bias[cb + 1];
        #pragma unroll
        for (int mi = 0; mi < 2; mi++) {
            int r0 = bm + wm + mi * 16 + (t >> 2);
            *(uint32_t*)(C + (size_t)r0 * N + cb) =
                pack_bf16(c[mi][nj][0] + bz0, c[mi][nj][1] + bz1);
            *(uint32_t*)(C + (size_t)(r0 + 8) * N + cb) =
                pack_bf16(c[mi][nj][2] + bz0, c[mi][nj][3] + bz1);
        }
    }
}

// ---------------- 3) causal flash attention v2: 128-row Q, cp.async pipeline --------
// 256 threads (8 warps) x 16 q-rows each. K/V 64-row tiles, double-buffered cp.async.
// smem: Q[128][264] + 2 x (K[64][264] + V[64][264]) bf16 = 202752 B dynamic.
#define FH_STRIDE 264
#define FAM_SMEM ((128 * FH_STRIDE + 4 * 64 * FH_STRIDE) * 2)

__device__ __forceinline__ void issue_kv(uint32_t smemBase,
                                         const __nv_bfloat16* base, int kt, int s,
                                         int tid) {
    const __nv_bfloat16* kptr = base + (size_t)(kt * 64) * 768;
    uint32_t kOff = smemBase + (uint32_t)((128 * FH_STRIDE + s * 2 * 64 * FH_STRIDE) * 2);
    uint32_t vOff = kOff + (uint32_t)(64 * FH_STRIDE * 2);
    #pragma unroll
    for (int p = 0; p < 8; p++) {
        int i = tid + p * 256;
        int row = i >> 5, c8 = (i & 31) << 3;
        uint32_t so = (uint32_t)((row * FH_STRIDE + c8) * 2);
        cp16(kOff + so, kptr + row * 768 + 256 + c8);
        cp16(vOff + so, kptr + row * 768 + 512 + c8);
    }
    asm volatile("cp.async.commit_group;");
}

__global__ __launch_bounds__(256, 1) void flash_mma_kernel(
        const __nv_bfloat16* __restrict__ qkv, __nv_bfloat16* __restrict__ outp) {
    extern __shared__ __nv_bfloat16 smb[];
    uint32_t smemBase = smem_u32(smb);

    int b = blockIdx.y;
    int qb = 7 - (int)blockIdx.x;      // heavy blocks scheduled first
    int tid = threadIdx.x;
    int w = tid >> 5, t = tid & 31;
    const __nv_bfloat16* base = qkv + (size_t)b * T_SZ * 768;
    const __nv_bfloat16* qbase = base + (size_t)(qb * 128) * 768;

    // load Q tile (128 rows, row-major) into smem region 0
    for (int p = 0; p < 16; p++) {
        int i = tid + p * 256;
        int row = i >> 5, c8 = (i & 31) << 3;
        *(uint4*)&smb[row * FH_STRIDE + c8] = *(const uint4*)(qbase + row * 768 + c8);
    }

    // per-lane ldmatrix offsets
    int rowA = (t & 7) + ((t >> 3) & 1) * 8;
    uint32_t aBase = smemBase +
        (uint32_t)(((16 * w + rowA) * FH_STRIDE + ((t >> 4) << 3)) * 2);
    int matB = t >> 3;
    uint32_t bLane =
        (uint32_t)((((t & 7) + (matB >> 1) * 8) * FH_STRIDE + ((matB & 1) << 3)) * 2);
    uint32_t vLane = (uint32_t)((rowA * FH_STRIDE + ((t >> 4) << 3)) * 2);

    float o[32][4];
    #pragma unroll
    for (int n = 0; n < 32; n++)
        #pragma unroll
        for (int e = 0; e < 4; e++) o[n][e] = 0.f;
    float m0 = -1e30f, m1 = -1e30f, l0 = 0.f, l1 = 0.f;

    int nt = 2 * qb + 2;
    issue_kv(smemBase, base, 0, 0, tid);

    for (int kt = 0; kt < nt; kt++) {
        int s = kt & 1;
        if (kt + 1 < nt) {
            issue_kv(smemBase, base, kt + 1, s ^ 1, tid);
            asm volatile("cp.async.wait_group 1;");
        } else {
            asm volatile("cp.async.wait_group 0;");
        }
        __syncthreads();

        // warp-uniform skip: tile entirely above this warp's rows
        bool skip = (64 * kt > 128 * qb + 16 * w + 15);
        if (!skip) {
            uint32_t kOff = smemBase +
                (uint32_t)((128 * FH_STRIDE + s * 2 * 64 * FH_STRIDE) * 2);
            uint32_t bBase = kOff + bLane;
            uint32_t vBase = kOff + (uint32_t)(64 * FH_STRIDE * 2) + vLane;

            float c[8][4];
            #pragma unroll
            for (int j = 0; j < 8; j++)
                #pragma unroll
                for (int e = 0; e < 4; e++) c[j][e] = 0.f;

            #pragma unroll
            for (int kf = 0; kf < 16; kf++) {
                uint32_t a0, a1, a2, a3;
                ldsm4(a0, a1, a2, a3, aBase + kf * 32);
                #pragma unroll
                for (int nf = 0; nf < 4; nf++) {
                    uint32_t b0, b1, b2, b3;
                    ldsm4(b0, b1, b2, b3,
                          bBase + nf * (16 * FH_STRIDE * 2) + kf * 32);
                    mma_bf16(c[2 * nf],     a0, a1, a2, a3, b0, b1);
                    mma_bf16(c[2 * nf + 1], a0, a1, a2, a3, b2, b3);
                }
            }

            #pragma unroll
            for (int j = 0; j < 8; j++)
                #pragma unroll
                for (int e = 0; e < 4; e++) c[j][e] *= 0.0625f;

            // causal mask on diagonal-overlap tiles (global indices)
            int rowg0 = 128 * qb + 16 * w + (t >> 2);
            int rowg1 = rowg0 + 8;
            if (64 * kt + 63 > 128 * qb + 16 * w) {
                #pragma unroll
                for (int j = 0; j < 8; j++) {
                    int colg = 64 * kt + 8 * j + (t & 3) * 2;
                    if (colg     > rowg0) c[j][0] = -1e30f;
                    if (colg + 1 > rowg0) c[j][1] = -1e30f;
                    if (colg     > rowg1) c[j][2] = -1e30f;
                    if (colg + 1 > rowg1) c[j][3] = -1e30f;
                }
            }

            // online softmax
            float mx0 = -1e30f, mx1 = -1e30f;
            #pragma unroll
            for (int j = 0; j < 8; j++) {
                mx0 = fmaxf(mx0, fmaxf(c[j][0], c[j][1]));
                mx1 = fmaxf(mx1, fmaxf(c[j][2], c[j][3]));
            }
            mx0 = fmaxf(mx0, __shfl_xor_sync(0xffffffffu, mx0, 1));
            mx0 = fmaxf(mx0, __shfl_xor_sync(0xffffffffu, mx0, 2));
            mx1 = fmaxf(mx1, __shfl_xor_sync(0xffffffffu, mx1, 1));
            mx1 = fmaxf(mx1, __shfl_xor_sync(0xffffffffu, mx1, 2));
            float mn0 = fmaxf(m0, mx0), mn1 = fmaxf(m1, mx1);
            float al0 = __expf(m0 - mn0), al1 = __expf(m1 - mn1);
            m0 = mn0; m1 = mn1;
            float s0 = 0.f, s1 = 0.f;
            #pragma unroll
            for (int j = 0; j < 8; j++) {
                c[j][0] = __expf(c[j][0] - mn0);
                c[j][1] = __expf(c[j][1] - mn0);
                c[j][2] = __expf(c[j][2] - mn1);
                c[j][3] = __expf(c[j][3] - mn1);
                s0 += c[j][0] + c[j][1];
                s1 += c[j][2] + c[j][3];
            }
            s0 += __shfl_xor_sync(0xffffffffu, s0, 1);
            s0 += __shfl_xor_sync(0xffffffffu, s0, 2);
            s1 += __shfl_xor_sync(0xffffffffu, s1, 1);
            s1 += __shfl_xor_sync(0xffffffffu, s1, 2);
            l0 = l0 * al0 + s0;
            l1 = l1 * al1 + s1;
            #pragma unroll
            for (int n = 0; n < 32; n++) {
                o[n][0] *= al0; o[n][1] *= al0;
                o[n][2] *= al1; o[n][3] *= al1;
            }

            uint32_t p[4][4];
            #pragma unroll
            for (int f = 0; f < 4; f++) {
                p[f][0] = pack_bf16(c[2 * f][0],     c[2 * f][1]);
                p[f][1] = pack_bf16(c[2 * f][2],     c[2 * f][3]);
                p[f][2] = pack_bf16(c[2 * f + 1][0], c[2 * f + 1][1]);
                p[f][3] = pack_bf16(c[2 * f + 1][2], c[2 * f + 1][3]);
            }

            #pragma unroll
            for (int f = 0; f < 4; f++) {
                #pragma unroll
                for (int nf = 0; nf < 16; nf++) {
                    uint32_t b0, b1, b2, b3;
                    ldsm4t(b0, b1, b2, b3,
                           vBase + f * (16 * FH_STRIDE * 2) + nf * 32);
                    mma_bf16(o[2 * nf],     p[f][0], p[f][1], p[f][2], p[f][3], b0, b1);
                    mma_bf16(o[2 * nf + 1], p[f][0], p[f][1], p[f][2], p[f][3], b2, b3);
                }
            }
        }
        __syncthreads();   // protect buf s^1 before next-iteration cp.async overwrites
    }

    float inv0 = 1.0f / l0, inv1 = 1.0f / l1;
    int gr0 = qb * 128 + 16 * w + (t >> 2);
    __nv_bfloat16* op0 = outp + ((size_t)b * T_SZ + gr0) * 256;
    __nv_bfloat16* op1 = op0 + 8 * 256;
    #pragma unroll
    for (int n = 0; n < 32; n++) {
        int col = 8 * n + (t & 3) * 2;
        *(uint32_t*)(op0 + col) = pack_bf16(o[n][0] * inv0, o[n][1] * inv0);
        *(uint32_t*)(op1 + col) = pack_bf16(o[n][2] * inv1, o[n][3] * inv1);
    }
}

// ---------------- 4) head GEMM (tensor cores) fused with shifted-target MSE ---------
// 128 tokens/CTA, 128 threads (4 warps x 32 rows). pred = X @ Wh + bh, then d^2 sums.
#define HD_XS 264
#define HD_WS 40
#define HEAD_SMEM ((128 * HD_XS + 256 * HD_WS) * 2)

__global__ __launch_bounds__(128) void head_mma_loss(
        const __nv_bfloat16* __restrict__ X, const __nv_bfloat16* __restrict__ Wh,
        const float* __restrict__ bh) {
    extern __shared__ __nv_bfloat16 hsm[];
    __nv_bfloat16* Xs = hsm;                 // [128][264]
    __nv_bfloat16* Ws = hsm + 128 * HD_XS;   // [256][40]
    int tid = threadIdx.x, w = tid >> 5, t = tid & 31;
    int tok0 = blockIdx.x * 128;

    // load X tile
    #pragma unroll
    for (int p = 0; p < 32; p++) {
        int i = tid + p * 128;
        int row = i >> 5, c8 = (i & 31) << 3;
        *(uint4*)&Xs[row * HD_XS + c8] =
            *(const uint4*)(X + (size_t)(tok0 + row) * 256 + c8);
    }
    // load Wh [256][32]
    #pragma unroll
    for (int p = 0; p < 8; p++) {
        int i = tid + p * 128;
        int row = i >> 2, c8 = (i & 3) << 3;
        *(uint4*)&Ws[row * HD_WS + c8] = *(const uint4*)(Wh + row * 32 + c8);
    }
    __syncthreads();

    int rowA = (t & 7) + ((t >> 3) & 1) * 8;
    uint32_t aBase = smem_u32(Xs) +
        (uint32_t)(((32 * w + rowA) * HD_XS + ((t >> 4) << 3)) * 2);
    uint32_t bBase = smem_u32(Ws) +
        (uint32_t)((rowA * HD_WS + ((t >> 4) << 3)) * 2);

    float c[2][4][4];
    #pragma unroll
    for (int mi = 0; mi < 2; mi++)
        #pragma unroll
        for (int nj = 0; nj < 4; nj++)
            #pragma unroll
            for (int e = 0; e < 4; e++) c[mi][nj][e] = 0.f;

    #pragma unroll
    for (int kf = 0; kf < 16; kf++) {
        uint32_t a0[2], a1[2], a2[2], a3[2];
        #pragma unroll
        for (int mi = 0; mi < 2; mi++)
            ldsm4(a0[mi], a1[mi], a2[mi], a3[mi],
                  aBase + mi * (16 * HD_XS * 2) + kf * 32);
        #pragma unroll
        for (int nn = 0; nn < 2; nn++) {
            uint32_t b0, b1, b2, b3;
            ldsm4t(b0, b1, b2, b3, bBase + kf * (16 * HD_WS * 2) + nn * 32);
            #pragma unroll
            for (int mi = 0; mi < 2; mi++) {
                mma_bf16(c[mi][2 * nn],     a0[mi], a1[mi], a2[mi], a3[mi], b0, b1);
                mma_bf16(c[mi][2 * nn + 1], a0[mi], a1[mi], a2[mi], a3[mi], b2, b3);
            }
        }
    }

    // bias + shifted-target squared error
    float d2 = 0.f;
    #pragma unroll
    for (int nj = 0; nj < 4; nj++) {
        int col = nj * 8 + (t & 3) * 2;
        float bz0 = __ldg(&bh[col]), bz1 = __ldg(&bh[col + 1]);
        #pragma unroll
        for (int mi = 0; mi < 2; mi++) {
            int r0 = tok0 + w * 32 + mi * 16 + (t >> 2);
            #pragma unroll
            for (int half = 0; half < 2; half++) {
                int rg = r0 + half * 8;
                int tt = rg & 1023, bb = rg >> 10;
                if (tt < T_SZ - 1) {
                    const float* tp = g_xn + (size_t)bb * L_SZ + (tt + 1) * PS_SZ + col;
                    float p0 = c[mi][nj][2 * half]     + bz0;
                    float p1 = c[mi][nj][2 * half + 1] + bz1;
                    float e0 = p0 - tp[0], e1 = p1 - tp[1];
                    d2 += e0 * e0 + e1 * e1;
                }
            }
        }
    }
    #pragma unroll
    for (int o = 16; o > 0; o >>= 1) d2 += __shfl_xor_sync(0xffffffffu, d2, o);
    __shared__ float red[4];
    if (t == 0) red[w] = d2;
    __syncthreads();
    if (tid == 0)
        g_partial[blockIdx.x] = red[0] + red[1] + red[2] + red[3];
}

__global__ __launch_bounds__(256) void finalize_kernel(float* __restrict__ out) {
    __shared__ double red[256];
    double s = (threadIdx.x < 256) ? (double)g_partial[threadIdx.x] : 0.0;
    red[threadIdx.x] = s;
    __syncthreads();
    for (int st = 128; st > 0; st >>= 1) {
        if (threadIdx.x < st) red[threadIdx.x] += red[threadIdx.x + st];
        __syncthreads();
    }
    if (threadIdx.x == 0)
        out[0] = (float)(red[0] / (double)((size_t)B_SZ * (T_SZ - 1) * PS_SZ));
}

// ---------------- launch ----------------
extern "C" void kernel_launch(void* const* d_in, const int* in_sizes, int n_in,
                              void* d_out, int out_size) {
    const float* x      = (const float*)d_in[0];
    const float* W_proj = (const float*)d_in[1];
    const float* b_proj = (const float*)d_in[2];
    const float* W_qkv  = (const float*)d_in[3];
    const float* b_qkv  = (const float*)d_in[4];
    const float* W_out  = (const float*)d_in[5];
    const float* b_out  = (const float*)d_in[6];
    const float* W_head = (const float*)d_in[7];
    const float* b_head = (const float*)d_in[8];

    __nv_bfloat16 *xnh, *hh, *qkvh, *attnh, *out2h, *Wp, *Wq, *Wo, *Wh;
    cudaGetSymbolAddress((void**)&xnh,   g_xnh);
    cudaGetSymbolAddress((void**)&hh,    g_hh);
    cudaGetSymbolAddress((void**)&qkvh,  g_qkvh);
    cudaGetSymbolAddress((void**)&attnh, g_attnh);
    cudaGetSymbolAddress((void**)&out2h, g_out2h);
    cudaGetSymbolAddress((void**)&Wp,    g_Wp);
    cudaGetSymbolAddress((void**)&Wq,    g_Wq);
    cudaGetSymbolAddress((void**)&Wo,    g_Wo);
    cudaGetSymbolAddress((void**)&Wh,    g_Wh);

    cudaFuncSetAttribute(flash_mma_kernel,
                         cudaFuncAttributeMaxDynamicSharedMemorySize, FAM_SMEM);
    cudaFuncSetAttribute(head_mma_loss,
                         cudaFuncAttributeMaxDynamicSharedMemorySize, HEAD_SMEM);

    // 0) weight conversions
    cvt_f2b<<<(PS_SZ * D_SZ / 4 + 255) / 256, 256>>>(W_proj, Wp, PS_SZ * D_SZ);
    cvt_f2b<<<(D_SZ * 3 * D_SZ / 4 + 255) / 256, 256>>>(W_qkv, Wq, D_SZ * 3 * D_SZ);
    cvt_f2b<<<(D_SZ * D_SZ / 4 + 255) / 256, 256>>>(W_out, Wo, D_SZ * D_SZ);
    cvt_f2b<<<(D_SZ * PS_SZ / 4 + 255) / 256, 256>>>(W_head, Wh, D_SZ * PS_SZ);
    // 1) instance norm (fp32 target + bf16 embed input)
    norm_kernel<<<B_SZ, 1024>>>(x);
    // 2) patch embedding
    hgemm_bias_bf16<<<dim3(2, 256), 256>>>(xnh, Wp, b_proj, hh, NTOK, D_SZ, PS_SZ);
    // 3) qkv
    hgemm_bias_bf16<<<dim3(6, 256), 256>>>(hh, Wq, b_qkv, qkvh, NTOK, 3 * D_SZ, D_SZ);
    // 4) causal flash attention v2 (cp.async pipelined)
    flash_mma_kernel<<<dim3(8, B_SZ), 256, FAM_SMEM>>>(qkvh, attnh);
    // 5) output projection
    hgemm_bias_bf16<<<dim3(2, 256), 256>>>(attnh, Wo, b_out, out2h, NTOK, D_SZ, D_SZ);
    // 6) head GEMM + shifted-MSE (tensor cores), 7) deterministic finalize
    head_mma_loss<<<NTOK / 128, 128, HEAD_SMEM>>>(out2h, Wh, b_head);
    finalize_kernel<<<1, 256>>>((float*)d_out);
}

// round 7
// speedup vs baseline: 7.3985x; 1.1809x over previous
#include <cuda_runtime.h>
#include <cuda_bf16.h>
#include <math.h>
#include <stdint.h>

#define B_SZ 32
#define L_SZ 32768
#define PS_SZ 32
#define T_SZ 1024
#define D_SZ 256
#define NTOK (B_SZ * T_SZ)   // 32768

// ---------------- scratch (no allocs allowed; BSS device globals) ----------------
__device__ float g_xn[B_SZ * L_SZ];                  // normalized series fp32 (loss target)
__device__ __nv_bfloat16 g_xnh[B_SZ * L_SZ];         // normalized series bf16 (embed input)
__device__ __nv_bfloat16 g_hh[NTOK * D_SZ];          // patch embedding bf16
__device__ __nv_bfloat16 g_qkvh[NTOK * 3 * D_SZ];    // qkv bf16
__device__ __nv_bfloat16 g_attnh[NTOK * D_SZ];       // attention out bf16
__device__ __nv_bfloat16 g_Wp[PS_SZ * D_SZ];         // W_proj bf16
__device__ __nv_bfloat16 g_Wq[D_SZ * 3 * D_SZ];      // W_qkv bf16
__device__ __nv_bfloat16 g_Woh[D_SZ * PS_SZ];        // W_out @ W_head, bf16
__device__ float g_boh[PS_SZ];                       // b_out @ W_head + b_head
__device__ float g_partial[4096];                    // per-block loss partials

// ---------------- small PTX helpers ----------------
__device__ __forceinline__ uint32_t smem_u32(const void* p) {
    uint32_t a;
    asm("{ .reg .u64 t; cvta.to.shared.u64 t, %1; cvt.u32.u64 %0, t; }"
        : "=r"(a) : "l"(p));
    return a;
}
__device__ __forceinline__ void ldsm4(uint32_t& r0, uint32_t& r1, uint32_t& r2,
                                      uint32_t& r3, uint32_t addr) {
    asm volatile("ldmatrix.sync.aligned.m8n8.x4.shared.b16 {%0,%1,%2,%3}, [%4];"
                 : "=r"(r0), "=r"(r1), "=r"(r2), "=r"(r3) : "r"(addr));
}
__device__ __forceinline__ void ldsm4t(uint32_t& r0, uint32_t& r1, uint32_t& r2,
                                       uint32_t& r3, uint32_t addr) {
    asm volatile("ldmatrix.sync.aligned.m8n8.x4.trans.shared.b16 {%0,%1,%2,%3}, [%4];"
                 : "=r"(r0), "=r"(r1), "=r"(r2), "=r"(r3) : "r"(addr));
}
__device__ __forceinline__ void mma_bf16(float* c, uint32_t a0, uint32_t a1,
                                         uint32_t a2, uint32_t a3,
                                         uint32_t b0, uint32_t b1) {
    asm volatile(
        "mma.sync.aligned.m16n8k16.row.col.f32.bf16.bf16.f32 "
        "{%0,%1,%2,%3}, {%4,%5,%6,%7}, {%8,%9}, {%0,%1,%2,%3};"
        : "+f"(c[0]), "+f"(c[1]), "+f"(c[2]), "+f"(c[3])
        : "r"(a0), "r"(a1), "r"(a2), "r"(a3), "r"(b0), "r"(b1));
}
__device__ __forceinline__ uint32_t pack_bf16(float lo, float hi) {
    uint32_t d;
    asm("cvt.rn.bf16x2.f32 %0, %1, %2;" : "=r"(d) : "f"(hi), "f"(lo));
    return d;
}
__device__ __forceinline__ void cp16(uint32_t saddr, const void* gaddr) {
    asm volatile("cp.async.cg.shared.global [%0], [%1], 16;"
                 :: "r"(saddr), "l"(gaddr));
}

// ---------------- 0a) fused weight conversion (W_proj + W_qkv) ----------------
__global__ void cvt_weights(const float* __restrict__ Wp, const float* __restrict__ Wq) {
    int q = blockIdx.x * 256 + threadIdx.x;     // 51200 quads total
    const float* src;
    __nv_bfloat16* dst;
    int idx;
    if (q < PS_SZ * D_SZ / 4) { src = Wp; dst = g_Wp; idx = q * 4; }
    else { src = Wq; dst = g_Wq; idx = (q - PS_SZ * D_SZ / 4) * 4; }
    float4 v = *(const float4*)(src + idx);
    __nv_bfloat16 t[4] = {__float2bfloat16(v.x), __float2bfloat16(v.y),
                          __float2bfloat16(v.z), __float2bfloat16(v.w)};
    *(uint2*)(dst + idx) = *(uint2*)t;
}

// ---------------- 0b) fold W_out into W_head: W_oh = W_out @ W_head ----------------
__global__ __launch_bounds__(256) void fuse_wo_wh(const float* __restrict__ Wo,
                                                  const float* __restrict__ Whd,
                                                  const float* __restrict__ bo,
                                                  const float* __restrict__ bhd) {
    int e = blockIdx.x * 256 + threadIdx.x;     // 8192 outputs
    int i = e >> 5, j = e & 31;
    float acc = 0.f;
    #pragma unroll 8
    for (int k = 0; k < 256; k++)
        acc += Wo[i * 256 + k] * Whd[k * 32 + j];
    g_Woh[e] = __float2bfloat16(acc);
    if (e < 32) {
        float b = 0.f;
        for (int k = 0; k < 256; k++) b += bo[k] * Whd[k * 32 + e];
        g_boh[e] = b + bhd[e];
    }
}

// ---------------- 1) instance norm over full series (ddof=1) ----------------
__global__ __launch_bounds__(1024) void norm_kernel(const float* __restrict__ x) {
    int b = blockIdx.x;
    const float* xr = x + (size_t)b * L_SZ;
    float s = 0.f, sq = 0.f;
    for (int i = threadIdx.x; i < L_SZ; i += 1024) {
        float v = xr[i];
        s += v; sq += v * v;
    }
    for (int o = 16; o > 0; o >>= 1) {
        s  += __shfl_xor_sync(0xffffffffu, s,  o);
        sq += __shfl_xor_sync(0xffffffffu, sq, o);
    }
    __shared__ float ss[32], ssq[32];
    __shared__ float sm_mean, sm_inv;
    int w = threadIdx.x >> 5;
    if ((threadIdx.x & 31) == 0) { ss[w] = s; ssq[w] = sq; }
    __syncthreads();
    if (threadIdx.x == 0) {
        float S = 0.f, SQ = 0.f;
        #pragma unroll
        for (int i = 0; i < 32; i++) { S += ss[i]; SQ += ssq[i]; }
        float mean = S / (float)L_SZ;
        float var = (SQ - (float)L_SZ * mean * mean) / (float)(L_SZ - 1);
        sm_mean = mean;
        sm_inv = 1.0f / (sqrtf(var) + 1e-5f);
    }
    __syncthreads();
    float mean = sm_mean, inv = sm_inv;
    float* op = g_xn + (size_t)b * L_SZ;
    __nv_bfloat16* oph = g_xnh + (size_t)b * L_SZ;
    for (int i = threadIdx.x; i < L_SZ; i += 1024) {
        float v = (xr[i] - mean) * inv;
        op[i] = v;
        oph[i] = __float2bfloat16(v);
    }
}

// ---------------- 2) bf16 tensor-core GEMM: C[M,N] = A[M,K] @ B[K,N] + bias ----------
#define AS_STRIDE 40
#define BS_STRIDE 136

__global__ __launch_bounds__(256) void hgemm_bias_bf16(
        const __nv_bfloat16* __restrict__ A, const __nv_bfloat16* __restrict__ Bm,
        const float* __restrict__ bias, __nv_bfloat16* __restrict__ C,
        int M, int N, int K) {
    __shared__ __nv_bfloat16 As[128 * AS_STRIDE];
    __shared__ __nv_bfloat16 Bs[32 * BS_STRIDE];
    int tid = threadIdx.x, w = tid >> 5, t = tid & 31;
    int bm = blockIdx.y * 128, bn = blockIdx.x * 128;
    int wm = (w & 3) * 32, wn = (w >> 2) * 64;

    int rowA = (t & 7) + ((t >> 3) & 1) * 8;
    uint32_t aBase = smem_u32(As) +
        (uint32_t)(((wm + rowA) * AS_STRIDE + ((t >> 4) << 3)) * 2);
    uint32_t bBase = smem_u32(Bs) +
        (uint32_t)((rowA * BS_STRIDE + wn + ((t >> 4) << 3)) * 2);

    float c[2][8][4];
    #pragma unroll
    for (int mi = 0; mi < 2; mi++)
        #pragma unroll
        for (int nj = 0; nj < 8; nj++)
            #pragma unroll
            for (int e = 0; e < 4; e++) c[mi][nj][e] = 0.f;

    for (int k0 = 0; k0 < K; k0 += 32) {
        #pragma unroll
        for (int p = 0; p < 2; p++) {
            int i = tid + p * 256;
            int r = i >> 2, cc = (i & 3) << 3;
            *(uint4*)&As[r * AS_STRIDE + cc] =
                *(const uint4*)(A + (size_t)(bm + r) * K + k0 + cc);
        }
        #pragma unroll
        for (int p = 0; p < 2; p++) {
            int i = tid + p * 256;
            int r = i >> 4, cc = (i & 15) << 3;
            *(uint4*)&Bs[r * BS_STRIDE + cc] =
                *(const uint4*)(Bm + (size_t)(k0 + r) * N + bn + cc);
        }
        __syncthreads();
        #pragma unroll
        for (int kf = 0; kf < 2; kf++) {
            uint32_t a0[2], a1[2], a2[2], a3[2];
            #pragma unroll
            for (int mi = 0; mi < 2; mi++)
                ldsm4(a0[mi], a1[mi], a2[mi], a3[mi],
                      aBase + mi * (16 * AS_STRIDE * 2) + kf * 32);
            #pragma unroll
            for (int nf = 0; nf < 4; nf++) {
                uint32_t b0, b1, b2, b3;
                ldsm4t(b0, b1, b2, b3,
                       bBase + kf * (16 * BS_STRIDE * 2) + nf * 32);
                #pragma unroll
                for (int mi = 0; mi < 2; mi++) {
                    mma_bf16(c[mi][2 * nf],     a0[mi], a1[mi], a2[mi], a3[mi], b0, b1);
                    mma_bf16(c[mi][2 * nf + 1], a0[mi], a1[mi], a2[mi], a3[mi], b2, b3);
                }
            }
        }
        __syncthreads();
    }

    #pragma unroll
    for (int nj = 0; nj < 8; nj++) {
        int cb = bn + wn + nj * 8 + (t & 3) * 2;
        float bz0 = bias[cb], bz1 = bias[cb + 1];
        #pragma unroll
        for (int mi = 0; mi < 2; mi++) {
            int r0 = bm + wm + mi * 16 + (t >> 2);
            *(uint32_t*)(C + (size_t)r0 * N + cb) =
                pack_bf16(c[mi][nj][0] + bz0, c[mi][nj][1] + bz1);
            *(uint32_t*)(C + (size_t)(r0 + 8) * N + cb) =
                pack_bf16(c[mi][nj][2] + bz0, c[mi][nj][3] + bz1);
        }
    }
}

// ---------------- 3) causal flash attention v3: paired q-blocks, cp.async ----------
// grid (4, 32): CTA x processes qb = 7-x then qb = x  (constant 18 tiles/CTA).
#define FH_STRIDE 264
#define FAM_SMEM ((128 * FH_STRIDE + 4 * 64 * FH_STRIDE) * 2)

__device__ __forceinline__ void issue_kv(uint32_t smemBase,
                                         const __nv_bfloat16* base, int kt, int s,
                                         int tid) {
    const __nv_bfloat16* kptr = base + (size_t)(kt * 64) * 768;
    uint32_t kOff = smemBase + (uint32_t)((128 * FH_STRIDE + s * 2 * 64 * FH_STRIDE) * 2);
    uint32_t vOff = kOff + (uint32_t)(64 * FH_STRIDE * 2);
    #pragma unroll
    for (int p = 0; p < 8; p++) {
        int i = tid + p * 256;
        int row = i >> 5, c8 = (i & 31) << 3;
        uint32_t so = (uint32_t)((row * FH_STRIDE + c8) * 2);
        cp16(kOff + so, kptr + row * 768 + 256 + c8);
        cp16(vOff + so, kptr + row * 768 + 512 + c8);
    }
    asm volatile("cp.async.commit_group;");
}

__global__ __launch_bounds__(256, 1) void flash_mma_kernel(
        const __nv_bfloat16* __restrict__ qkv, __nv_bfloat16* __restrict__ outp) {
    extern __shared__ __nv_bfloat16 smb[];
    uint32_t smemBase = smem_u32(smb);

    int b = blockIdx.y;
    int tid = threadIdx.x;
    int w = tid >> 5, t = tid & 31;
    const __nv_bfloat16* base = qkv + (size_t)b * T_SZ * 768;

    // per-lane ldmatrix offsets (invariant across passes)
    int rowA = (t & 7) + ((t >> 3) & 1) * 8;
    uint32_t aBase = smemBase +
        (uint32_t)(((16 * w + rowA) * FH_STRIDE + ((t >> 4) << 3)) * 2);
    int matB = t >> 3;
    uint32_t bLane =
        (uint32_t)((((t & 7) + (matB >> 1) * 8) * FH_STRIDE + ((matB & 1) << 3)) * 2);
    uint32_t vLane = (uint32_t)((rowA * FH_STRIDE + ((t >> 4) << 3)) * 2);

    #pragma unroll 1
    for (int pass = 0; pass < 2; pass++) {
        int qb = pass ? (int)blockIdx.x : 7 - (int)blockIdx.x;
        const __nv_bfloat16* qbase = base + (size_t)(qb * 128) * 768;

        // load Q tile (visibility covered by first in-loop __syncthreads)
        for (int p = 0; p < 16; p++) {
            int i = tid + p * 256;
            int row = i >> 5, c8 = (i & 31) << 3;
            *(uint4*)&smb[row * FH_STRIDE + c8] =
                *(const uint4*)(qbase + row * 768 + c8);
        }

        float o[32][4];
        #pragma unroll
        for (int n = 0; n < 32; n++)
            #pragma unroll
            for (int e = 0; e < 4; e++) o[n][e] = 0.f;
        float m0 = -1e30f, m1 = -1e30f, l0 = 0.f, l1 = 0.f;

        int nt = 2 * qb + 2;
        issue_kv(smemBase, base, 0, 0, tid);

        for (int kt = 0; kt < nt; kt++) {
            int s = kt & 1;
            if (kt + 1 < nt) {
                issue_kv(smemBase, base, kt + 1, s ^ 1, tid);
                asm volatile("cp.async.wait_group 1;");
            } else {
                asm volatile("cp.async.wait_group 0;");
            }
            __syncthreads();

            bool skip = (64 * kt > 128 * qb + 16 * w + 15);
            if (!skip) {
                uint32_t kOff = smemBase +
                    (uint32_t)((128 * FH_STRIDE + s * 2 * 64 * FH_STRIDE) * 2);
                uint32_t bBase = kOff + bLane;
                uint32_t vBase = kOff + (uint32_t)(64 * FH_STRIDE * 2) + vLane;

                float c[8][4];
                #pragma unroll
                for (int j = 0; j < 8; j++)
                    #pragma unroll
                    for (int e = 0; e < 4; e++) c[j][e] = 0.f;

                #pragma unroll
                for (int kf = 0; kf < 16; kf++) {
                    uint32_t a0, a1, a2, a3;
                    ldsm4(a0, a1, a2, a3, aBase + kf * 32);
                    #pragma unroll
                    for (int nf = 0; nf < 4; nf++) {
                        uint32_t b0, b1, b2, b3;
                        ldsm4(b0, b1, b2, b3,
                              bBase + nf * (16 * FH_STRIDE * 2) + kf * 32);
                        mma_bf16(c[2 * nf],     a0, a1, a2, a3, b0, b1);
                        mma_bf16(c[2 * nf + 1], a0, a1, a2, a3, b2, b3);
                    }
                }

                #pragma unroll
                for (int j = 0; j < 8; j++)
                    #pragma unroll
                    for (int e = 0; e < 4; e++) c[j][e] *= 0.0625f;

                int rowg0 = 128 * qb + 16 * w + (t >> 2);
                int rowg1 = rowg0 + 8;
                if (64 * kt + 63 > 128 * qb + 16 * w) {
                    #pragma unroll
                    for (int j = 0; j < 8; j++) {
                        int colg = 64 * kt + 8 * j + (t & 3) * 2;
                        if (colg     > rowg0) c[j][0] = -1e30f;
                        if (colg + 1 > rowg0) c[j][1] = -1e30f;
                        if (colg     > rowg1) c[j][2] = -1e30f;
                        if (colg + 1 > rowg1) c[j][3] = -1e30f;
                    }
                }

                float mx0 = -1e30f, mx1 = -1e30f;
                #pragma unroll
                for (int j = 0; j < 8; j++) {
                    mx0 = fmaxf(mx0, fmaxf(c[j][0], c[j][1]));
                    mx1 = fmaxf(mx1, fmaxf(c[j][2], c[j][3]));
                }
                mx0 = fmaxf(mx0, __shfl_xor_sync(0xffffffffu, mx0, 1));
                mx0 = fmaxf(mx0, __shfl_xor_sync(0xffffffffu, mx0, 2));
                mx1 = fmaxf(mx1, __shfl_xor_sync(0xffffffffu, mx1, 1));
                mx1 = fmaxf(mx1, __shfl_xor_sync(0xffffffffu, mx1, 2));
                float mn0 = fmaxf(m0, mx0), mn1 = fmaxf(m1, mx1);
                float al0 = __expf(m0 - mn0), al1 = __expf(m1 - mn1);
                m0 = mn0; m1 = mn1;
                float s0 = 0.f, s1 = 0.f;
                #pragma unroll
                for (int j = 0; j < 8; j++) {
                    c[j][0] = __expf(c[j][0] - mn0);
                    c[j][1] = __expf(c[j][1] - mn0);
                    c[j][2] = __expf(c[j][2] - mn1);
                    c[j][3] = __expf(c[j][3] - mn1);
                    s0 += c[j][0] + c[j][1];
                    s1 += c[j][2] + c[j][3];
                }
                s0 += __shfl_xor_sync(0xffffffffu, s0, 1);
                s0 += __shfl_xor_sync(0xffffffffu, s0, 2);
                s1 += __shfl_xor_sync(0xffffffffu, s1, 1);
                s1 += __shfl_xor_sync(0xffffffffu, s1, 2);
                l0 = l0 * al0 + s0;
                l1 = l1 * al1 + s1;
                #pragma unroll
                for (int n = 0; n < 32; n++) {
                    o[n][0] *= al0; o[n][1] *= al0;
                    o[n][2] *= al1; o[n][3] *= al1;
                }

                uint32_t p[4][4];
                #pragma unroll
                for (int f = 0; f < 4; f++) {
                    p[f][0] = pack_bf16(c[2 * f][0],     c[2 * f][1]);
                    p[f][1] = pack_bf16(c[2 * f][2],     c[2 * f][3]);
                    p[f][2] = pack_bf16(c[2 * f + 1][0], c[2 * f + 1][1]);
                    p[f][3] = pack_bf16(c[2 * f + 1][2], c[2 * f + 1][3]);
                }

                #pragma unroll
                for (int f = 0; f < 4; f++) {
                    #pragma unroll
                    for (int nf = 0; nf < 16; nf++) {
                        uint32_t b0, b1, b2, b3;
                        ldsm4t(b0, b1, b2, b3,
                               vBase + f * (16 * FH_STRIDE * 2) + nf * 32);
                        mma_bf16(o[2 * nf],     p[f][0], p[f][1], p[f][2], p[f][3],
                                 b0, b1);
                        mma_bf16(o[2 * nf + 1], p[f][0], p[f][1], p[f][2], p[f][3],
                                 b2, b3);
                    }
                }
            }
            __syncthreads();   // protect buffers before next-iteration cp.async
        }

        float inv0 = 1.0f / l0, inv1 = 1.0f / l1;
        int gr0 = qb * 128 + 16 * w + (t >> 2);
        __nv_bfloat16* op0 = outp + ((size_t)b * T_SZ + gr0) * 256;
        __nv_bfloat16* op1 = op0 + 8 * 256;
        #pragma unroll
        for (int n = 0; n < 32; n++) {
            int col = 8 * n + (t & 3) * 2;
            *(uint32_t*)(op0 + col) = pack_bf16(o[n][0] * inv0, o[n][1] * inv0);
            *(uint32_t*)(op1 + col) = pack_bf16(o[n][2] * inv1, o[n][3] * inv1);
        }
    }
}

// ---------------- 4) head GEMM (tensor cores, W_out folded) + shifted-target MSE ----
#define HD_XS 264
#define HD_WS 40
#define HEAD_SMEM ((128 * HD_XS + 256 * HD_WS) * 2)

__global__ __launch_bounds__(128) void head_mma_loss(
        const __nv_bfloat16* __restrict__ X, const __nv_bfloat16* __restrict__ Wh,
        const float* __restrict__ bh) {
    extern __shared__ __nv_bfloat16 hsm[];
    __nv_bfloat16* Xs = hsm;                 // [128][264]
    __nv_bfloat16* Ws = hsm + 128 * HD_XS;   // [256][40]
    int tid = threadIdx.x, w = tid >> 5, t = tid & 31;
    int tok0 = blockIdx.x * 128;

    #pragma unroll
    for (int p = 0; p < 32; p++) {
        int i = tid + p * 128;
        int row = i >> 5, c8 = (i & 31) << 3;
        *(uint4*)&Xs[row * HD_XS + c8] =
            *(const uint4*)(X + (size_t)(tok0 + row) * 256 + c8);
    }
    #pragma unroll
    for (int p = 0; p < 8; p++) {
        int i = tid + p * 128;
        int row = i >> 2, c8 = (i & 3) << 3;
        *(uint4*)&Ws[row * HD_WS + c8] = *(const uint4*)(Wh + row * 32 + c8);
    }
    __syncthreads();

    int rowA = (t & 7) + ((t >> 3) & 1) * 8;
    uint32_t aBase = smem_u32(Xs) +
        (uint32_t)(((32 * w + rowA) * HD_XS + ((t >> 4) << 3)) * 2);
    uint32_t bBase = smem_u32(Ws) +
        (uint32_t)((rowA * HD_WS + ((t >> 4) << 3)) * 2);

    float c[2][4][4];
    #pragma unroll
    for (int mi = 0; mi < 2; mi++)
        #pragma unroll
        for (int nj = 0; nj < 4; nj++)
            #pragma unroll
            for (int e = 0; e < 4; e++) c[mi][nj][e] = 0.f;

    #pragma unroll
    for (int kf = 0; kf < 16; kf++) {
        uint32_t a0[2], a1[2], a2[2], a3[2];
        #pragma unroll
        for (int mi = 0; mi < 2; mi++)
            ldsm4(a0[mi], a1[mi], a2[mi], a3[mi],
                  aBase + mi * (16 * HD_XS * 2) + kf * 32);
        #pragma unroll
        for (int nn = 0; nn < 2; nn++) {
            uint32_t b0, b1, b2, b3;
            ldsm4t(b0, b1, b2, b3, bBase + kf * (16 * HD_WS * 2) + nn * 32);
            #pragma unroll
            for (int mi = 0; mi < 2; mi++) {
                mma_bf16(c[mi][2 * nn],     a0[mi], a1[mi], a2[mi], a3[mi], b0, b1);
                mma_bf16(c[mi][2 * nn + 1], a0[mi], a1[mi], a2[mi], a3[mi], b2, b3);
            }
        }
    }

    float d2 = 0.f;
    #pragma unroll
    for (int nj = 0; nj < 4; nj++) {
        int col = nj * 8 + (t & 3) * 2;
        float bz0 = __ldg(&bh[col]), bz1 = __ldg(&bh[col + 1]);
        #pragma unroll
        for (int mi = 0; mi < 2; mi++) {
            int r0 = tok0 + w * 32 + mi * 16 + (t >> 2);
            #pragma unroll
            for (int half = 0; half < 2; half++) {
                int rg = r0 + half * 8;
                int tt = rg & 1023, bb = rg >> 10;
                if (tt < T_SZ - 1) {
                    const float* tp = g_xn + (size_t)bb * L_SZ + (tt + 1) * PS_SZ + col;
                    float p0 = c[mi][nj][2 * half]     + bz0;
                    float p1 = c[mi][nj][2 * half + 1] + bz1;
                    float e0 = p0 - tp[0], e1 = p1 - tp[1];
                    d2 += e0 * e0 + e1 * e1;
                }
            }
        }
    }
    #pragma unroll
    for (int o = 16; o > 0; o >>= 1) d2 += __shfl_xor_sync(0xffffffffu, d2, o);
    __shared__ float red[4];
    if (t == 0) red[w] = d2;
    __syncthreads();
    if (tid == 0)
        g_partial[blockIdx.x] = red[0] + red[1] + red[2] + red[3];
}

__global__ __launch_bounds__(256) void finalize_kernel(float* __restrict__ out) {
    __shared__ double red[256];
    double s = (threadIdx.x < 256) ? (double)g_partial[threadIdx.x] : 0.0;
    red[threadIdx.x] = s;
    __syncthreads();
    for (int st = 128; st > 0; st >>= 1) {
        if (threadIdx.x < st) red[threadIdx.x] += red[threadIdx.x + st];
        __syncthreads();
    }
    if (threadIdx.x == 0)
        out[0] = (float)(red[0] / (double)((size_t)B_SZ * (T_SZ - 1) * PS_SZ));
}

// ---------------- launch ----------------
extern "C" void kernel_launch(void* const* d_in, const int* in_sizes, int n_in,
                              void* d_out, int out_size) {
    const float* x      = (const float*)d_in[0];
    const float* W_proj = (const float*)d_in[1];
    const float* b_proj = (const float*)d_in[2];
    const float* W_qkv  = (const float*)d_in[3];
    const float* b_qkv  = (const float*)d_in[4];
    const float* W_out  = (const float*)d_in[5];
    const float* b_out  = (const float*)d_in[6];
    const float* W_head = (const float*)d_in[7];
    const float* b_head = (const float*)d_in[8];

    __nv_bfloat16 *xnh, *hh, *qkvh, *attnh, *Wp, *Wq, *Woh;
    float* boh;
    cudaGetSymbolAddress((void**)&xnh,   g_xnh);
    cudaGetSymbolAddress((void**)&hh,    g_hh);
    cudaGetSymbolAddress((void**)&qkvh,  g_qkvh);
    cudaGetSymbolAddress((void**)&attnh, g_attnh);
    cudaGetSymbolAddress((void**)&Wp,    g_Wp);
    cudaGetSymbolAddress((void**)&Wq,    g_Wq);
    cudaGetSymbolAddress((void**)&Woh,   g_Woh);
    cudaGetSymbolAddress((void**)&boh,   g_boh);

    cudaFuncSetAttribute(flash_mma_kernel,
                         cudaFuncAttributeMaxDynamicSharedMemorySize, FAM_SMEM);
    cudaFuncSetAttribute(head_mma_loss,
                         cudaFuncAttributeMaxDynamicSharedMemorySize, HEAD_SMEM);

    // 0) weight prep (conversion + W_out/W_head folding)
    cvt_weights<<<(PS_SZ * D_SZ / 4 + D_SZ * 3 * D_SZ / 4) / 256, 256>>>(W_proj, W_qkv);
    fuse_wo_wh<<<D_SZ * PS_SZ / 256, 256>>>(W_out, W_head, b_out, b_head);
    // 1) instance norm (fp32 target + bf16 embed input)
    norm_kernel<<<B_SZ, 1024>>>(x);
    // 2) patch embedding
    hgemm_bias_bf16<<<dim3(2, 256), 256>>>(xnh, Wp, b_proj, hh, NTOK, D_SZ, PS_SZ);
    // 3) qkv
    hgemm_bias_bf16<<<dim3(6, 256), 256>>>(hh, Wq, b_qkv, qkvh, NTOK, 3 * D_SZ, D_SZ);
    // 4) causal flash attention v3 (paired q-blocks, single balanced wave)
    flash_mma_kernel<<<dim3(4, B_SZ), 256, FAM_SMEM>>>(qkvh, attnh);
    // 5) head GEMM (W_out folded in) + shifted-MSE, 6) deterministic finalize
    head_mma_loss<<<NTOK / 128, 128, HEAD_SMEM>>>(attnh, Woh, boh);
    finalize_kernel<<<1, 256>>>((float*)d_out);
}